// round 8
// baseline (speedup 1.0000x reference)
#include <cuda_runtime.h>

// ---------------------------------------------------------------------------
// RobustStateSpaceSimulatorAugmented: B=1024 rows, T=256 sequential steps.
// 128 CTAs x 512 threads, 8 rows per CTA, rows packed in pairs into f32x2.
//
// Numerics FROZEN: XLA EmitFastTanh, each dot = single ascending-k fp32x2 FMA
// chain, bias after dot, gate math op-for-op. This round: weights pre-packed/
// pre-duplicated in a prep kernel (zero-padded to uniform din — fma(0,x,acc)
// is an exact no-op), vectorized L2 dots, 5 barriers/step, h/hb L2 chains
// overlapped with output stores.
// ---------------------------------------------------------------------------

namespace {
constexpr int B_  = 1024;
constexpr int T_  = 256;
constexpr int NXF_ = 64;
constexpr int NXB_ = 32;
constexpr int NU_  = 16;
constexpr int NY_  = 16;
constexpr int NTH_ = 8;
constexpr int HID_ = 512;

constexpr int BM = 8;
constexpr int P  = BM / 2;
constexpr int NT = 512;

constexpr int DIN_F  = NXF_ + NU_  + NTH_;  // 88
constexpr int DIN_FB = NXF_ + NXB_ + NU_;   // 112 (padded width for f group)
constexpr int DIN_H  = NXF_ + NTH_;         // 72
constexpr int DIN_HB = NXF_ + NXB_;         // 96  (padded width for h group)

constexpr long OFF_XF = 0;
constexpr long OFF_XB = OFF_XF + (long)B_ * T_ * NXF_;
constexpr long OFF_Y  = OFF_XB + (long)B_ * T_ * NXB_;
constexpr long OFF_XP = OFF_Y  + (long)B_ * T_ * NY_;
} // namespace

typedef unsigned long long ull;

// ---------------------------------------------------------------------------
// packed weight scratch (written by prep_kernel every launch; deterministic)
// ---------------------------------------------------------------------------
__device__ ull g_w1fgb[DIN_FB * HID_ * 4];   // per (k,j): (wf,wf),(wfb,wfb),(wgb,wgb),0
__device__ ull g_w1hhb[DIN_HB * HID_ * 2];   // per (k,j): (wh,wh),(whb,whb)
__device__ ull g_w2f [HID_ * NXF_];          // dup f32x2 of W2, [k][j] layout
__device__ ull g_w2fb[HID_ * NXF_];
__device__ ull g_w2gb[HID_ * NXB_];
__device__ ull g_w2h [HID_ * NY_];
__device__ ull g_w2hb[HID_ * NY_];

// ---------------------------------------------------------------------------
// f32x2 helpers
// ---------------------------------------------------------------------------
__device__ __forceinline__ ull pack2(float w) {
    ull r;
    asm("mov.b64 %0, {%1, %1};" : "=l"(r) : "f"(w));
    return r;
}

__device__ __forceinline__ float2 unpack2(ull v) {
    float2 r;
    asm("mov.b64 {%0, %1}, %2;" : "=f"(r.x), "=f"(r.y) : "l"(v));
    return r;
}

__device__ __forceinline__ void ffma2(ull& acc, ull a, ull b) {
    asm("fma.rn.f32x2 %0, %1, %2, %0;" : "+l"(acc) : "l"(a), "l"(b));
}

__device__ __forceinline__ float clipf(float v, float lo, float hi) {
    return fminf(fmaxf(v, lo), hi);
}

// XLA f32 tanh (EmitFastTanh / Eigen ptanh) — numerics frozen
__device__ __forceinline__ float xla_tanh(float x) {
    const float kMax = 7.90531110763549805f;
    float xc = fminf(fmaxf(x, -kMax), kMax);
    float x2 = xc * xc;
    float n = -2.76076847742355e-16f;
    n = fmaf(x2, n,  2.00018790482477e-13f);
    n = fmaf(x2, n, -8.60467152213735e-11f);
    n = fmaf(x2, n,  5.12229709037114e-08f);
    n = fmaf(x2, n,  1.48572235717979e-05f);
    n = fmaf(x2, n,  6.37261928875436e-04f);
    n = fmaf(x2, n,  4.89352455891786e-03f);
    n = xc * n;
    float d = 1.19825839466702e-06f;
    d = fmaf(x2, d, 1.18534705686654e-04f);
    d = fmaf(x2, d, 2.26843463243900e-03f);
    d = fmaf(x2, d, 4.89352518554385e-03f);
    float r = n / d;
    return fabsf(x) < 0.0004f ? x : r;
}

__device__ __forceinline__ float2 tanh2(ull acc, float bb) {
    float2 v = unpack2(acc);
    return make_float2(xla_tanh(v.x + bb), xla_tanh(v.y + bb));
}

// ---------------------------------------------------------------------------
// prep kernel: pack + duplicate + zero-pad weights into scratch
// ---------------------------------------------------------------------------
__global__ void prep_kernel(const float* __restrict__ fW1,  const float* __restrict__ fbW1,
                            const float* __restrict__ gbW1, const float* __restrict__ hW1,
                            const float* __restrict__ hbW1, const float* __restrict__ fW2,
                            const float* __restrict__ fbW2, const float* __restrict__ gbW2,
                            const float* __restrict__ hW2,  const float* __restrict__ hbW2) {
    int idx = blockIdx.x * blockDim.x + threadIdx.x;
    if (idx < DIN_FB * HID_) {              // region 1: f/fb/gb L1 (zero-pad f)
        int k = idx >> 9, j = idx & 511;
        float wf = (k < DIN_F) ? fW1[k * HID_ + j] : 0.0f;
        ull* d = &g_w1fgb[(size_t)idx * 4];
        d[0] = pack2(wf);
        d[1] = pack2(fbW1[k * HID_ + j]);
        d[2] = pack2(gbW1[k * HID_ + j]);
        d[3] = 0ull;
    }
    if (idx < DIN_HB * HID_) {              // region 2: h/hb L1 (zero-pad h)
        int k = idx >> 9, j = idx & 511;
        float wh = (k < DIN_H) ? hW1[k * HID_ + j] : 0.0f;
        g_w1hhb[(size_t)idx * 2]     = pack2(wh);
        g_w1hhb[(size_t)idx * 2 + 1] = pack2(hbW1[k * HID_ + j]);
    }
    // region 3: dup W2 arrays
    if (idx < HID_ * NXF_)  g_w2f [idx] = pack2(fW2[idx]);
    if (idx < HID_ * NXF_)  g_w2fb[idx] = pack2(fbW2[idx]);
    if (idx < HID_ * NXB_)  g_w2gb[idx] = pack2(gbW2[idx]);
    if (idx < HID_ * NY_)   g_w2h [idx] = pack2(hW2[idx]);
    if (idx < HID_ * NY_)   g_w2hb[idx] = pack2(hbW2[idx]);
}

// ---------------------------------------------------------------------------
// shared memory
// ---------------------------------------------------------------------------
struct __align__(16) SmemX {
    float2 in_f [DIN_FB * P];  // [0,64) xp | [64,80) u | [80,88) thf | [88,112) zero
    float2 in_fb[DIN_FB * P];  // [0,64) xp | [64,96) xb | [96,112) u
    float2 in_h [DIN_HB * P];  // [0,64) xp | [64,72) thh | [72,96) zero
    float2 in_hb[DIN_HB * P];  // [0,64) xf | [64,96) xb   (PRE-clip values)
    float2 hidf [P * HID_];
    float2 hidfb[P * HID_];
    float2 hidgb[P * HID_];
    float2 hidh [P * HID_];
    float2 hidhb[P * HID_];
    float2 xp[P * NXF_], xf[P * NXF_];
    float2 xb[P * NXB_], mu[P * NXB_], sig[P * NXB_];
    float2 fo[P * NXF_], fbo[P * NXF_], gbo[P * NXB_];
    float2 yoh[P * NY_], yohb[P * NY_];
};

// ---------------------------------------------------------------------------
// L2 dots on dup weights: single ascending-k chain (numerics frozen)
// ---------------------------------------------------------------------------
template <int DOUT>
__device__ __forceinline__ float2 dot512d(const ull* __restrict__ W2d,
                                          const float* __restrict__ b2,
                                          const ulonglong2* __restrict__ hp2, int j) {
    const ull* w = W2d + j;
    ull acc = 0ull;
#pragma unroll 4
    for (int k2 = 0; k2 < HID_ / 2; k2++) {
        ull w0 = __ldg(w); w += DOUT;
        ull w1 = __ldg(w); w += DOUT;
        ulonglong2 h = hp2[k2];
        ffma2(acc, w0, h.x);
        ffma2(acc, w1, h.y);
    }
    float2 s = unpack2(acc);
    float bb = __ldg(b2 + j);
    s.x += bb; s.y += bb;
    return s;
}

template <int DA, int DB>
__device__ __forceinline__ void dot512d_dual(
        const ull* __restrict__ WA, const float* __restrict__ bA,
        const ulonglong2* __restrict__ hpA, int jA, float2& outA,
        const ull* __restrict__ WB, const float* __restrict__ bB,
        const ulonglong2* __restrict__ hpB, int jB, float2& outB) {
    const ull* wa = WA + jA;
    const ull* wb = WB + jB;
    ull aA = 0ull, aB = 0ull;
#pragma unroll 4
    for (int k2 = 0; k2 < HID_ / 2; k2++) {
        ull wa0 = __ldg(wa); wa += DA;
        ull wa1 = __ldg(wa); wa += DA;
        ull wb0 = __ldg(wb); wb += DB;
        ull wb1 = __ldg(wb); wb += DB;
        ulonglong2 hA = hpA[k2], hB = hpB[k2];
        ffma2(aA, wa0, hA.x); ffma2(aA, wa1, hA.y);
        ffma2(aB, wb0, hB.x); ffma2(aB, wb1, hB.y);
    }
    outA = unpack2(aA); float ba = __ldg(bA + jA); outA.x += ba; outA.y += ba;
    outB = unpack2(aB); float bb = __ldg(bB + jB); outB.x += bb; outB.y += bb;
}

// gating + mu/sigma (op-for-op vs reference)
__device__ __forceinline__ void gate_update(float xb, float mu, float sig, float gbv,
                                            float t1, float t2, float xblo, float xbhi,
                                            float& xbn, float& mun, float& sgn) {
    float inv_gp  = 1.0f / sig;
    float inv_gp2 = 1.0f / (sig * sig);
    float xmmu = xb - mu;
    float delta1 = gbv * (xmmu + (gbv * 0.5f) * (1.0f + inv_gp));
    float delta2 = 1.0f - inv_gp;
    float delta = delta1 * delta2;
    float eps = t2 * (sig * sig - t2 / t1)
              + xmmu * (xmmu + gbv * (1.0f + inv_gp)
                        + (gbv * gbv * 0.5f) * (1.0f + inv_gp2));
    float d2e2 = delta * delta - eps * eps;
    bool c = ((eps >= delta) && (delta >= 0.0f))
          || ((eps <  delta) && (delta <  0.0f))
          || ((delta < eps)  && (eps  <  0.0f))
          || (((2.0f * t2 * t2 / t1) * eps >= d2e2) && (d2e2 > 0.0f));
    float gamma = c ? sig : 1.0f;
    float dxb = gbv / gamma;
    xbn = dxb;
    float xbc = fminf(fmaxf(dxb, xblo), xbhi);
    float c1 = t1 / t2;
    float c2 = 1.0f / t2;
    mun = c1 * mu + c2 * xbc;
    float dm = xbc - mun;
    sgn = sqrtf(c1 * (sig * sig) + c2 * (dm * dm));
}

// ---------------------------------------------------------------------------
// phase D: fused h/hb L1 (uniform k<96, h zero-padded)
// ---------------------------------------------------------------------------
__device__ __forceinline__ void phaseD(SmemX& sm, int tid,
                                       const float* __restrict__ hb1,
                                       const float* __restrict__ hbb1) {
    const int j = tid;
    const ulonglong2* wq = reinterpret_cast<const ulonglong2*>(g_w1hhb) + j;
    const ulonglong2* inh = reinterpret_cast<const ulonglong2*>(sm.in_h);
    const ulonglong2* inb = reinterpret_cast<const ulonglong2*>(sm.in_hb);
    ull ah0 = 0, ah1 = 0, ah2 = 0, ah3 = 0;
    ull ab0 = 0, ab1 = 0, ab2 = 0, ab3 = 0;
#pragma unroll 2
    for (int k = 0; k < DIN_HB; k++) {
        ulonglong2 w = __ldg(wq); wq += HID_;
        ulonglong2 ha = inh[2 * k], hc = inh[2 * k + 1];
        ulonglong2 ba = inb[2 * k], bc = inb[2 * k + 1];
        ffma2(ah0, w.x, ha.x); ffma2(ah1, w.x, ha.y);
        ffma2(ah2, w.x, hc.x); ffma2(ah3, w.x, hc.y);
        ffma2(ab0, w.y, ba.x); ffma2(ab1, w.y, ba.y);
        ffma2(ab2, w.y, bc.x); ffma2(ab3, w.y, bc.y);
    }
    float bh = __ldg(hb1 + j), bb = __ldg(hbb1 + j);
    sm.hidh [0 * HID_ + j] = tanh2(ah0, bh);
    sm.hidh [1 * HID_ + j] = tanh2(ah1, bh);
    sm.hidh [2 * HID_ + j] = tanh2(ah2, bh);
    sm.hidh [3 * HID_ + j] = tanh2(ah3, bh);
    sm.hidhb[0 * HID_ + j] = tanh2(ab0, bb);
    sm.hidhb[1 * HID_ + j] = tanh2(ab1, bb);
    sm.hidhb[2 * HID_ + j] = tanh2(ab2, bb);
    sm.hidhb[3 * HID_ + j] = tanh2(ab3, bb);
}

// ---------------------------------------------------------------------------
// phase E: h/hb L2 chains + y store (threads 0-127, private bar.sync 1) |
// x stores + clipped-state scatter (128-447) | u prefetch (448-511)
// ---------------------------------------------------------------------------
__device__ __forceinline__ void phaseE(SmemX& sm, float* __restrict__ out,
                                       const float* __restrict__ u, int b0,
                                       int ti, int t_next, int tid, bool doclip,
                                       const float* __restrict__ hb2_,
                                       const float* __restrict__ hbb2,
                                       float xlo, float xhi, float xblo,
                                       float xbhi, float ylo, float yhi) {
    if (tid < 128) {
        const bool isH = tid < 64;
        const int tA = isH ? tid : tid - 64;
        const int j = tA & 15, p = tA >> 4;
        const ulonglong2* hp2 = reinterpret_cast<const ulonglong2*>(
            (isH ? sm.hidh : sm.hidhb) + p * HID_);
        float2 r = dot512d<NY_>(isH ? g_w2h : g_w2hb, isH ? hb2_ : hbb2, hp2, j);
        (isH ? sm.yoh : sm.yohb)[p * NY_ + j] = r;
        asm volatile("bar.sync 1, 128;" ::: "memory");
        int bm = tid >> 4, i = tid & 15;
        int si = (((bm >> 1) * NY_ + i) << 1) | (bm & 1);
        float v = reinterpret_cast<float*>(sm.yoh)[si]
                + reinterpret_cast<float*>(sm.yohb)[si];
        if (doclip) v = clipf(v, ylo, yhi);
        out[OFF_Y + ((size_t)(b0 + bm) * T_ + ti) * NY_ + i] = v;
    } else if (tid < 384) {
#pragma unroll
        for (int r = 0; r < 2; r++) {
            int e = ((tid - 128) << 1) | r;
            int bm = e >> 6, i = e & 63;
            int p = bm >> 1, lane = bm & 1;
            int si = ((p * NXF_ + i) << 1) | lane;
            float vf = reinterpret_cast<float*>(sm.xf)[si];
            float vp = reinterpret_cast<float*>(sm.xp)[si];
            if (doclip) {
                vf = clipf(vf, xlo, xhi); vp = clipf(vp, xlo, xhi);
                reinterpret_cast<float*>(sm.xf)[si] = vf;
                reinterpret_cast<float*>(sm.xp)[si] = vp;
            }
            size_t base = ((size_t)(b0 + bm) * T_ + ti);
            out[OFF_XF + base * NXF_ + i] = vf;
            out[OFF_XP + base * NXF_ + i] = vp;
            // clipped xp feeds next step's f / fb inputs
            reinterpret_cast<float*>(sm.in_f )[(((i << 2) | p) << 1) | lane] = vp;
            reinterpret_cast<float*>(sm.in_fb)[(((i << 2) | p) << 1) | lane] = vp;
        }
    } else if (tid < 448) {
#pragma unroll
        for (int r = 0; r < 4; r++) {
            int e = ((tid - 384) << 2) | r;
            int bm = e >> 5, i = e & 31;
            int p = bm >> 1, lane = bm & 1;
            int si = ((p * NXB_ + i) << 1) | lane;
            float v = reinterpret_cast<float*>(sm.xb)[si];
            if (doclip) { v = clipf(v, xblo, xbhi);
                          reinterpret_cast<float*>(sm.xb)[si] = v; }
            out[OFF_XB + ((size_t)(b0 + bm) * T_ + ti) * NXB_ + i] = v;
            reinterpret_cast<float*>(sm.in_fb)[((((64 + i) << 2) | p) << 1) | lane] = v;
        }
    } else {
#pragma unroll
        for (int r = 0; r < 2; r++) {
            int e = ((tid - 448) << 1) | r;
            int bm = e >> 4, i = e & 15;
            int p = bm >> 1, lane = bm & 1;
            float v = u[((size_t)(b0 + bm) * T_ + t_next) * NU_ + i];
            reinterpret_cast<float*>(sm.in_f )[((((64 + i) << 2) | p) << 1) | lane] = v;
            reinterpret_cast<float*>(sm.in_fb)[((((96 + i) << 2) | p) << 1) | lane] = v;
        }
    }
}

// ---------------------------------------------------------------------------
// main persistent kernel
// ---------------------------------------------------------------------------
__global__ void __launch_bounds__(NT, 1)
sim_kernel(const float* __restrict__ xf0, const float* __restrict__ xb0,
           const float* __restrict__ u,   const float* __restrict__ thfg,
           const float* __restrict__ thhg,
           const float* __restrict__ fb1,  const float* __restrict__ fb2_,
           const float* __restrict__ fbb1, const float* __restrict__ fbb2,
           const float* __restrict__ gbb1, const float* __restrict__ gbb2,
           const float* __restrict__ hb1,  const float* __restrict__ hb2_,
           const float* __restrict__ hbb1, const float* __restrict__ hbb2,
           const float* __restrict__ pxlo, const float* __restrict__ pxhi,
           const float* __restrict__ pxblo,const float* __restrict__ pxbhi,
           const float* __restrict__ pylo, const float* __restrict__ pyhi,
           float* __restrict__ out) {
    extern __shared__ __align__(16) char dynraw[];
    SmemX& sm = *reinterpret_cast<SmemX*>(dynraw);

    const int tid = threadIdx.x;
    const int b0  = blockIdx.x * BM;
    const float xlo = pxlo[0], xhi = pxhi[0];
    const float xblo = pxblo[0], xbhi = pxbhi[0];
    const float ylo = pylo[0], yhi = pyhi[0];

    // ---- prologue: initial state + static input segments ----
    {   // xf0 -> xp/xf state + scatter into in_f/in_fb/in_h/in_hb (512 elems)
        int bm = tid >> 6, i = tid & 63;
        int p = bm >> 1, lane = bm & 1;
        float v = xf0[(b0 + bm) * NXF_ + i];
        int si = ((p * NXF_ + i) << 1) | lane;
        reinterpret_cast<float*>(sm.xf)[si] = v;
        reinterpret_cast<float*>(sm.xp)[si] = v;
        int ii = (((i << 2) | p) << 1) | lane;
        reinterpret_cast<float*>(sm.in_f )[ii] = v;
        reinterpret_cast<float*>(sm.in_fb)[ii] = v;
        reinterpret_cast<float*>(sm.in_h )[ii] = v;
        reinterpret_cast<float*>(sm.in_hb)[ii] = v;
    }
    if (tid < 256) {   // xb0 + mu/sig init + scatter
        int bm = tid >> 5, i = tid & 31;
        int p = bm >> 1, lane = bm & 1;
        float v = xb0[(b0 + bm) * NXB_ + i];
        int si = ((p * NXB_ + i) << 1) | lane;
        reinterpret_cast<float*>(sm.xb)[si]  = v;
        reinterpret_cast<float*>(sm.mu)[si]  = 0.0f;
        reinterpret_cast<float*>(sm.sig)[si] = 1.0f;
        int ii = ((((64 + i) << 2) | p) << 1) | lane;
        reinterpret_cast<float*>(sm.in_fb)[ii] = v;
        reinterpret_cast<float*>(sm.in_hb)[ii] = v;
    }
    if (tid < 64) {    // thetas into static input slots
        int bm = tid >> 3, i = tid & 7;
        int p = bm >> 1, lane = bm & 1;
        reinterpret_cast<float*>(sm.in_f)[((((80 + i) << 2) | p) << 1) | lane] =
            thfg[(b0 + bm) * NTH_ + i];
        reinterpret_cast<float*>(sm.in_h)[((((64 + i) << 2) | p) << 1) | lane] =
            thhg[(b0 + bm) * NTH_ + i];
    }
    if (tid < 96) {    // zero padding: in_f k in [88,112)
        int k = 88 + (tid >> 2), p = tid & 3;
        sm.in_f[(k << 2) | p] = make_float2(0.0f, 0.0f);
    } else if (tid < 192) {  // zero padding: in_h k in [72,96)
        int q = tid - 96;
        int k = 72 + (q >> 2), p = q & 3;
        sm.in_h[(k << 2) | p] = make_float2(0.0f, 0.0f);
    }
    __syncthreads();

    // ---- y0 = h(x_f_0) + h_b(x_f_0, x_b_0), stored (unclipped) at t=0 ----
    phaseD(sm, tid, hb1, hbb1);
    __syncthreads();
    phaseE(sm, out, u, b0, 0, 0, tid, false,
           hb2_, hbb2, xlo, xhi, xblo, xbhi, ylo, yhi);
    __syncthreads();

    // ---- main recurrence ----
    for (int t = 0; t < T_ - 1; t++) {
        const float tf = (float)t;

        // phase A: fused L1 of f + fb + gb (uniform k<112, f zero-padded)
        {
            const int j = tid;
            const ulonglong2* wq =
                reinterpret_cast<const ulonglong2*>(g_w1fgb) + 2 * j;
            const ulonglong2* inf = reinterpret_cast<const ulonglong2*>(sm.in_f);
            const ulonglong2* inb = reinterpret_cast<const ulonglong2*>(sm.in_fb);
            ull af0 = 0, af1 = 0, af2 = 0, af3 = 0;
            ull ab0 = 0, ab1 = 0, ab2 = 0, ab3 = 0;
            ull ag0 = 0, ag1 = 0, ag2 = 0, ag3 = 0;
#pragma unroll 2
            for (int k = 0; k < DIN_FB; k++) {
                ulonglong2 wA = __ldg(wq);       // (wf,wfb)
                ulonglong2 wB = __ldg(wq + 1);   // (wgb,0)
                wq += 2 * HID_;
                ulonglong2 fa = inf[2 * k], fc = inf[2 * k + 1];
                ulonglong2 ba = inb[2 * k], bc = inb[2 * k + 1];
                ffma2(af0, wA.x, fa.x); ffma2(af1, wA.x, fa.y);
                ffma2(af2, wA.x, fc.x); ffma2(af3, wA.x, fc.y);
                ffma2(ab0, wA.y, ba.x); ffma2(ab1, wA.y, ba.y);
                ffma2(ab2, wA.y, bc.x); ffma2(ab3, wA.y, bc.y);
                ffma2(ag0, wB.x, ba.x); ffma2(ag1, wB.x, ba.y);
                ffma2(ag2, wB.x, bc.x); ffma2(ag3, wB.x, bc.y);
            }
            float bf = __ldg(fb1 + j), bb = __ldg(fbb1 + j), bg = __ldg(gbb1 + j);
            sm.hidf [0 * HID_ + j] = tanh2(af0, bf);
            sm.hidf [1 * HID_ + j] = tanh2(af1, bf);
            sm.hidf [2 * HID_ + j] = tanh2(af2, bf);
            sm.hidf [3 * HID_ + j] = tanh2(af3, bf);
            sm.hidfb[0 * HID_ + j] = tanh2(ab0, bb);
            sm.hidfb[1 * HID_ + j] = tanh2(ab1, bb);
            sm.hidfb[2 * HID_ + j] = tanh2(ab2, bb);
            sm.hidfb[3 * HID_ + j] = tanh2(ab3, bb);
            sm.hidgb[0 * HID_ + j] = tanh2(ag0, bg);
            sm.hidgb[1 * HID_ + j] = tanh2(ag1, bg);
            sm.hidgb[2 * HID_ + j] = tanh2(ag2, bg);
            sm.hidgb[3 * HID_ + j] = tanh2(ag3, bg);
        }
        __syncthreads();

        // phase B: fused L2 of f (256 tasks) + fb (256) + gb (128 dual)
        {
            const bool isF = tid < 256;
            const int tA = isF ? tid : tid - 256;
            const int jA = tA & 63, pA = tA >> 6;
            const ull* WA = isF ? g_w2f : g_w2fb;
            const float* bA = isF ? fb2_ : fbb2;
            const ulonglong2* hpA = reinterpret_cast<const ulonglong2*>(
                (isF ? sm.hidf : sm.hidfb) + pA * HID_);
            float2* outA = isF ? sm.fo : sm.fbo;
            if (tid < 128) {
                const int jB = tid & 31, pB = tid >> 5;
                const ulonglong2* hpB = reinterpret_cast<const ulonglong2*>(
                    sm.hidgb + pB * HID_);
                float2 rA, rB;
                dot512d_dual<NXF_, NXB_>(WA, bA, hpA, jA, rA,
                                         g_w2gb, gbb2, hpB, jB, rB);
                outA[pA * NXF_ + jA] = rA;
                sm.gbo[pB * NXB_ + jB] = rB;
            } else {
                outA[pA * NXF_ + jA] = dot512d<NXF_>(WA, bA, hpA, jA);
            }
        }
        __syncthreads();

        // phase C: gate + state update; scatter PRE-clip values into in_h/in_hb
        if (tid < 128) {
            int q = tid, p = q >> 5, i = q & 31;
            float2 xb2 = sm.xb[q], mu2 = sm.mu[q], sg2 = sm.sig[q], gb2 = sm.gbo[q];
            float xbn, mun, sgn;
            gate_update(xb2.x, mu2.x, sg2.x, gb2.x, tf + 1.0f, tf + 2.0f,
                        xblo, xbhi, xbn, mun, sgn);
            xb2.x = xbn; mu2.x = mun; sg2.x = sgn;
            gate_update(xb2.y, mu2.y, sg2.y, gb2.y, tf + 1.0f, tf + 2.0f,
                        xblo, xbhi, xbn, mun, sgn);
            xb2.y = xbn; mu2.y = mun; sg2.y = sgn;
            sm.xb[q] = xb2; sm.mu[q] = mu2; sm.sig[q] = sg2;
            sm.in_hb[((64 + i) << 2) | p] = xb2;        // pre-clip xb_n
        } else if (tid < 384) {
            int q = tid - 128, p = q >> 6, i = q & 63;
            float2 xp2 = sm.xp[q], xf2 = sm.xf[q], f2 = sm.fo[q], fb2 = sm.fbo[q];
            float dfx = f2.x + fb2.x, dfy = f2.y + fb2.y;
            float2 xpn = make_float2(xp2.x + f2.x, xp2.y + f2.y);
            float2 xfn = make_float2(xf2.x + dfx, xf2.y + dfy);
            sm.xp[q] = xpn; sm.xf[q] = xfn;
            sm.in_h [(i << 2) | p] = xpn;               // pre-clip xp_n
            sm.in_hb[(i << 2) | p] = xfn;               // pre-clip xf_n
        }
        __syncthreads();

        // phase D: fused h/hb L1
        phaseD(sm, tid, hb1, hbb1);
        __syncthreads();

        // phase E: h/hb L2 + y store | x stores + clipped scatter | u prefetch
        phaseE(sm, out, u, b0, t + 1, t + 1, tid, true,
               hb2_, hbb2, xlo, xhi, xblo, xbhi, ylo, yhi);
        __syncthreads();
    }
}

// ---------------------------------------------------------------------------
extern "C" void kernel_launch(void* const* d_in, const int* in_sizes, int n_in,
                              void* d_out, int out_size) {
    (void)in_sizes; (void)n_in; (void)out_size;
    const float* xf0  = (const float*)d_in[0];
    const float* xb0  = (const float*)d_in[1];
    const float* uu   = (const float*)d_in[2];
    const float* thf  = (const float*)d_in[3];
    const float* thh  = (const float*)d_in[4];
    const float* fW1  = (const float*)d_in[5];
    const float* fb1  = (const float*)d_in[6];
    const float* fW2  = (const float*)d_in[7];
    const float* fb2  = (const float*)d_in[8];
    const float* fbW1 = (const float*)d_in[9];
    const float* fbb1 = (const float*)d_in[10];
    const float* fbW2 = (const float*)d_in[11];
    const float* fbb2 = (const float*)d_in[12];
    const float* gbW1 = (const float*)d_in[13];
    const float* gbb1 = (const float*)d_in[14];
    const float* gbW2 = (const float*)d_in[15];
    const float* gbb2 = (const float*)d_in[16];
    const float* hW1  = (const float*)d_in[17];
    const float* hb1  = (const float*)d_in[18];
    const float* hW2  = (const float*)d_in[19];
    const float* hb2  = (const float*)d_in[20];
    const float* hbW1 = (const float*)d_in[21];
    const float* hbb1 = (const float*)d_in[22];
    const float* hbW2 = (const float*)d_in[23];
    const float* hbb2 = (const float*)d_in[24];
    const float* xlo  = (const float*)d_in[25];
    const float* xhi  = (const float*)d_in[26];
    const float* xblo = (const float*)d_in[27];
    const float* xbhi = (const float*)d_in[28];
    const float* ylo  = (const float*)d_in[29];
    const float* yhi  = (const float*)d_in[30];

    // pack weights into scratch (deterministic, graph-capturable)
    int prep_total = DIN_FB * HID_;   // largest region (57344) covers all
    prep_kernel<<<(prep_total + 511) / 512, 512>>>(
        fW1, fbW1, gbW1, hW1, hbW1, fW2, fbW2, gbW2, hW2, hbW2);

    cudaFuncSetAttribute(sim_kernel,
                         cudaFuncAttributeMaxDynamicSharedMemorySize,
                         (int)sizeof(SmemX));
    sim_kernel<<<B_ / BM, NT, sizeof(SmemX)>>>(
        xf0, xb0, uu, thf, thh,
        fb1, fb2, fbb1, fbb2, gbb1, gbb2,
        hb1, hb2, hbb1, hbb2,
        xlo, xhi, xblo, xbhi, ylo, yhi,
        (float*)d_out);
}

// round 9
// speedup vs baseline: 1.3745x; 1.3745x over previous
#include <cuda_runtime.h>

// ---------------------------------------------------------------------------
// RobustStateSpaceSimulatorAugmented: B=1024 rows, T=256 sequential steps.
// 128 CTAs x 512 threads, 8 rows per CTA, rows packed in pairs into f32x2.
//
// Numerics FROZEN: XLA EmitFastTanh, each dot = single ascending-k fp32x2 FMA
// chain, bias after dot, gate math op-for-op.
// R9: compact coalesced W1 loads (revert R8 layout), dup'd W2 only,
// y-dot chains merged into next step's phase B (no lonely-warp chains),
// y store in phase C on otherwise-idle threads, phase E = stores only.
// ---------------------------------------------------------------------------

namespace {
constexpr int B_  = 1024;
constexpr int T_  = 256;
constexpr int NXF_ = 64;
constexpr int NXB_ = 32;
constexpr int NU_  = 16;
constexpr int NY_  = 16;
constexpr int NTH_ = 8;
constexpr int HID_ = 512;

constexpr int BM = 8;
constexpr int P  = BM / 2;
constexpr int NT = 512;

constexpr int DIN_F  = NXF_ + NU_  + NTH_;  // 88
constexpr int DIN_FB = NXF_ + NXB_ + NU_;   // 112
constexpr int DIN_H  = NXF_ + NTH_;         // 72
constexpr int DIN_HB = NXF_ + NXB_;         // 96

constexpr long OFF_XF = 0;
constexpr long OFF_XB = OFF_XF + (long)B_ * T_ * NXF_;
constexpr long OFF_Y  = OFF_XB + (long)B_ * T_ * NXB_;
constexpr long OFF_XP = OFF_Y  + (long)B_ * T_ * NY_;
} // namespace

typedef unsigned long long ull;

// packed (duplicated f32x2) W2 scratch — written by prep_kernel each launch
__device__ ull g_w2f [HID_ * NXF_];
__device__ ull g_w2fb[HID_ * NXF_];
__device__ ull g_w2gb[HID_ * NXB_];
__device__ ull g_w2h [HID_ * NY_];
__device__ ull g_w2hb[HID_ * NY_];

// ---------------------------------------------------------------------------
// f32x2 helpers
// ---------------------------------------------------------------------------
__device__ __forceinline__ ull pack2(float w) {
    ull r;
    asm("mov.b64 %0, {%1, %1};" : "=l"(r) : "f"(w));
    return r;
}

__device__ __forceinline__ float2 unpack2(ull v) {
    float2 r;
    asm("mov.b64 {%0, %1}, %2;" : "=f"(r.x), "=f"(r.y) : "l"(v));
    return r;
}

__device__ __forceinline__ void ffma2(ull& acc, ull a, ull b) {
    asm("fma.rn.f32x2 %0, %1, %2, %0;" : "+l"(acc) : "l"(a), "l"(b));
}

__device__ __forceinline__ float clipf(float v, float lo, float hi) {
    return fminf(fmaxf(v, lo), hi);
}

// XLA f32 tanh (EmitFastTanh / Eigen ptanh) — numerics frozen
__device__ __forceinline__ float xla_tanh(float x) {
    const float kMax = 7.90531110763549805f;
    float xc = fminf(fmaxf(x, -kMax), kMax);
    float x2 = xc * xc;
    float n = -2.76076847742355e-16f;
    n = fmaf(x2, n,  2.00018790482477e-13f);
    n = fmaf(x2, n, -8.60467152213735e-11f);
    n = fmaf(x2, n,  5.12229709037114e-08f);
    n = fmaf(x2, n,  1.48572235717979e-05f);
    n = fmaf(x2, n,  6.37261928875436e-04f);
    n = fmaf(x2, n,  4.89352455891786e-03f);
    n = xc * n;
    float d = 1.19825839466702e-06f;
    d = fmaf(x2, d, 1.18534705686654e-04f);
    d = fmaf(x2, d, 2.26843463243900e-03f);
    d = fmaf(x2, d, 4.89352518554385e-03f);
    float r = n / d;
    return fabsf(x) < 0.0004f ? x : r;
}

__device__ __forceinline__ float2 tanh2(ull acc, float bb) {
    float2 v = unpack2(acc);
    return make_float2(xla_tanh(v.x + bb), xla_tanh(v.y + bb));
}

// prep: duplicate W2 into f32x2 pairs (coalesced 8B/lane loads later)
__global__ void prep_kernel(const float* __restrict__ fW2,
                            const float* __restrict__ fbW2,
                            const float* __restrict__ gbW2,
                            const float* __restrict__ hW2,
                            const float* __restrict__ hbW2) {
    int idx = blockIdx.x * blockDim.x + threadIdx.x;
    if (idx < HID_ * NXF_) {
        g_w2f [idx] = pack2(fW2 [idx]);
        g_w2fb[idx] = pack2(fbW2[idx]);
    }
    if (idx < HID_ * NXB_) g_w2gb[idx] = pack2(gbW2[idx]);
    if (idx < HID_ * NY_) {
        g_w2h [idx] = pack2(hW2 [idx]);
        g_w2hb[idx] = pack2(hbW2[idx]);
    }
}

// ---------------------------------------------------------------------------
// shared memory (~107 KB, 1 CTA/SM)
// ---------------------------------------------------------------------------
struct __align__(16) SmemX {
    float2 in_f [DIN_F  * P];  // [0,64) xp | [64,80) u | [80,88) thf
    float2 in_fb[DIN_FB * P];  // [0,64) xp | [64,96) xb | [96,112) u
    float2 in_h [DIN_H  * P];  // [0,64) xp | [64,72) thh
    float2 in_hb[DIN_HB * P];  // [0,64) xf | [64,96) xb   (PRE-clip)
    float2 hidf [P * HID_];
    float2 hidfb[P * HID_];
    float2 hidgb[P * HID_];
    float2 hidh [P * HID_];
    float2 hidhb[P * HID_];
    float2 xp[P * NXF_], xf[P * NXF_];
    float2 xb[P * NXB_], mu[P * NXB_], sig[P * NXB_];
    float2 fo[P * NXF_], fbo[P * NXF_], gbo[P * NXB_];
    float2 yoh[P * NY_], yohb[P * NY_];
};

// ---------------------------------------------------------------------------
// L2 dots on dup weights: single ascending-k chain (numerics frozen)
// ---------------------------------------------------------------------------
template <int DOUT>
__device__ __forceinline__ float2 dot512d(const ull* __restrict__ W2d,
                                          const float* __restrict__ b2,
                                          const ulonglong2* __restrict__ hp2, int j) {
    const ull* w = W2d + j;
    ull acc = 0ull;
#pragma unroll 4
    for (int k2 = 0; k2 < HID_ / 2; k2++) {
        ull w0 = __ldg(w); w += DOUT;
        ull w1 = __ldg(w); w += DOUT;
        ulonglong2 h = hp2[k2];
        ffma2(acc, w0, h.x);
        ffma2(acc, w1, h.y);
    }
    float2 s = unpack2(acc);
    float bb = __ldg(b2 + j);
    s.x += bb; s.y += bb;
    return s;
}

template <int DA, int DB>
__device__ __forceinline__ void dot512d_dual(
        const ull* __restrict__ WA, const float* __restrict__ bA,
        const ulonglong2* __restrict__ hpA, int jA, float2& outA,
        const ull* __restrict__ WB, const float* __restrict__ bB,
        const ulonglong2* __restrict__ hpB, int jB, float2& outB) {
    const ull* wa = WA + jA;
    const ull* wb = WB + jB;
    ull aA = 0ull, aB = 0ull;
#pragma unroll 4
    for (int k2 = 0; k2 < HID_ / 2; k2++) {
        ull wa0 = __ldg(wa); wa += DA;
        ull wa1 = __ldg(wa); wa += DA;
        ull wb0 = __ldg(wb); wb += DB;
        ull wb1 = __ldg(wb); wb += DB;
        ulonglong2 hA = hpA[k2], hB = hpB[k2];
        ffma2(aA, wa0, hA.x); ffma2(aA, wa1, hA.y);
        ffma2(aB, wb0, hB.x); ffma2(aB, wb1, hB.y);
    }
    outA = unpack2(aA); float ba = __ldg(bA + jA); outA.x += ba; outA.y += ba;
    outB = unpack2(aB); float bb = __ldg(bB + jB); outB.x += bb; outB.y += bb;
}

// gating + mu/sigma (op-for-op vs reference; numerics frozen)
__device__ __forceinline__ void gate_update(float xb, float mu, float sig, float gbv,
                                            float t1, float t2, float xblo, float xbhi,
                                            float& xbn, float& mun, float& sgn) {
    float inv_gp  = 1.0f / sig;
    float inv_gp2 = 1.0f / (sig * sig);
    float xmmu = xb - mu;
    float delta1 = gbv * (xmmu + (gbv * 0.5f) * (1.0f + inv_gp));
    float delta2 = 1.0f - inv_gp;
    float delta = delta1 * delta2;
    float eps = t2 * (sig * sig - t2 / t1)
              + xmmu * (xmmu + gbv * (1.0f + inv_gp)
                        + (gbv * gbv * 0.5f) * (1.0f + inv_gp2));
    float d2e2 = delta * delta - eps * eps;
    bool c = ((eps >= delta) && (delta >= 0.0f))
          || ((eps <  delta) && (delta <  0.0f))
          || ((delta < eps)  && (eps  <  0.0f))
          || (((2.0f * t2 * t2 / t1) * eps >= d2e2) && (d2e2 > 0.0f));
    float gamma = c ? sig : 1.0f;
    float dxb = gbv / gamma;
    xbn = dxb;
    float xbc = fminf(fmaxf(dxb, xblo), xbhi);
    float c1 = t1 / t2;
    float c2 = 1.0f / t2;
    mun = c1 * mu + c2 * xbc;
    float dm = xbc - mun;
    sgn = sqrtf(c1 * (sig * sig) + c2 * (dm * dm));
}

// ---------------------------------------------------------------------------
// phase D: fused h/hb L1, compact coalesced scalar weight loads
// ---------------------------------------------------------------------------
__device__ __forceinline__ void phaseD(SmemX& sm, int tid,
                                       const float* __restrict__ hW1,
                                       const float* __restrict__ hbW1,
                                       const float* __restrict__ hb1,
                                       const float* __restrict__ hbb1) {
    const int j = tid;
    const float* wh = hW1 + j;
    const float* wb = hbW1 + j;
    const ulonglong2* inh = reinterpret_cast<const ulonglong2*>(sm.in_h);
    const ulonglong2* inb = reinterpret_cast<const ulonglong2*>(sm.in_hb);
    ull ah0 = 0, ah1 = 0, ah2 = 0, ah3 = 0;
    ull ab0 = 0, ab1 = 0, ab2 = 0, ab3 = 0;
#pragma unroll 2
    for (int k = 0; k < DIN_H; k++) {
        ull wwh = pack2(__ldg(wh)); wh += HID_;
        ull wwb = pack2(__ldg(wb)); wb += HID_;
        ulonglong2 ha = inh[2 * k], hc = inh[2 * k + 1];
        ulonglong2 ba = inb[2 * k], bc = inb[2 * k + 1];
        ffma2(ah0, wwh, ha.x); ffma2(ah1, wwh, ha.y);
        ffma2(ah2, wwh, hc.x); ffma2(ah3, wwh, hc.y);
        ffma2(ab0, wwb, ba.x); ffma2(ab1, wwb, ba.y);
        ffma2(ab2, wwb, bc.x); ffma2(ab3, wwb, bc.y);
    }
#pragma unroll 4
    for (int k = DIN_H; k < DIN_HB; k++) {
        ull wwb = pack2(__ldg(wb)); wb += HID_;
        ulonglong2 ba = inb[2 * k], bc = inb[2 * k + 1];
        ffma2(ab0, wwb, ba.x); ffma2(ab1, wwb, ba.y);
        ffma2(ab2, wwb, bc.x); ffma2(ab3, wwb, bc.y);
    }
    float bh = __ldg(hb1 + j), bb = __ldg(hbb1 + j);
    sm.hidh [0 * HID_ + j] = tanh2(ah0, bh);
    sm.hidh [1 * HID_ + j] = tanh2(ah1, bh);
    sm.hidh [2 * HID_ + j] = tanh2(ah2, bh);
    sm.hidh [3 * HID_ + j] = tanh2(ah3, bh);
    sm.hidhb[0 * HID_ + j] = tanh2(ab0, bb);
    sm.hidhb[1 * HID_ + j] = tanh2(ab1, bb);
    sm.hidhb[2 * HID_ + j] = tanh2(ab2, bb);
    sm.hidhb[3 * HID_ + j] = tanh2(ab3, bb);
}

// ---------------------------------------------------------------------------
// phase E: x stores (+clip, + scatter clipped into in_f/in_fb) + u prefetch
// ---------------------------------------------------------------------------
__device__ __forceinline__ void phaseE(SmemX& sm, float* __restrict__ out,
                                       const float* __restrict__ u, int b0,
                                       int ti, int t_next, int tid, bool doclip,
                                       float xlo, float xhi, float xblo, float xbhi) {
    if (tid < 256) {
#pragma unroll
        for (int r = 0; r < 2; r++) {
            int e = (tid << 1) | r;
            int bm = e >> 6, i = e & 63;
            int p = bm >> 1, lane = bm & 1;
            int si = ((p * NXF_ + i) << 1) | lane;
            float vf = reinterpret_cast<float*>(sm.xf)[si];
            float vp = reinterpret_cast<float*>(sm.xp)[si];
            if (doclip) {
                vf = clipf(vf, xlo, xhi); vp = clipf(vp, xlo, xhi);
                reinterpret_cast<float*>(sm.xf)[si] = vf;
                reinterpret_cast<float*>(sm.xp)[si] = vp;
            }
            size_t base = ((size_t)(b0 + bm) * T_ + ti);
            out[OFF_XF + base * NXF_ + i] = vf;
            out[OFF_XP + base * NXF_ + i] = vp;
            reinterpret_cast<float*>(sm.in_f )[(((i << 2) | p) << 1) | lane] = vp;
            reinterpret_cast<float*>(sm.in_fb)[(((i << 2) | p) << 1) | lane] = vp;
        }
    } else if (tid < 384) {
#pragma unroll
        for (int r = 0; r < 2; r++) {
            int e = (((tid - 256) << 1) | r);
            int bm = e >> 5, i = e & 31;
            int p = bm >> 1, lane = bm & 1;
            int si = ((p * NXB_ + i) << 1) | lane;
            float v = reinterpret_cast<float*>(sm.xb)[si];
            if (doclip) { v = clipf(v, xblo, xbhi);
                          reinterpret_cast<float*>(sm.xb)[si] = v; }
            out[OFF_XB + ((size_t)(b0 + bm) * T_ + ti) * NXB_ + i] = v;
            reinterpret_cast<float*>(sm.in_fb)[((((64 + i) << 2) | p) << 1) | lane] = v;
        }
    } else {   // u[:, t_next, :] into in_f [64,80) and in_fb [96,112)
        int e = tid - 384;
        int bm = e >> 4, i = e & 15;
        int p = bm >> 1, lane = bm & 1;
        float v = u[((size_t)(b0 + bm) * T_ + t_next) * NU_ + i];
        reinterpret_cast<float*>(sm.in_f )[((((64 + i) << 2) | p) << 1) | lane] = v;
        reinterpret_cast<float*>(sm.in_fb)[((((96 + i) << 2) | p) << 1) | lane] = v;
    }
}

// ---------------------------------------------------------------------------
// main persistent kernel
// ---------------------------------------------------------------------------
__global__ void __launch_bounds__(NT, 1)
sim_kernel(const float* __restrict__ xf0, const float* __restrict__ xb0,
           const float* __restrict__ u,   const float* __restrict__ thfg,
           const float* __restrict__ thhg,
           const float* __restrict__ fW1,  const float* __restrict__ fb1,
           const float* __restrict__ fbW1, const float* __restrict__ fbb1,
           const float* __restrict__ gbW1, const float* __restrict__ gbb1,
           const float* __restrict__ hW1,  const float* __restrict__ hb1,
           const float* __restrict__ hbW1, const float* __restrict__ hbb1,
           const float* __restrict__ fb2_, const float* __restrict__ fbb2,
           const float* __restrict__ gbb2, const float* __restrict__ hb2_,
           const float* __restrict__ hbb2,
           const float* __restrict__ pxlo, const float* __restrict__ pxhi,
           const float* __restrict__ pxblo,const float* __restrict__ pxbhi,
           const float* __restrict__ pylo, const float* __restrict__ pyhi,
           float* __restrict__ out) {
    extern __shared__ __align__(16) char dynraw[];
    SmemX& sm = *reinterpret_cast<SmemX*>(dynraw);

    const int tid = threadIdx.x;
    const int b0  = blockIdx.x * BM;
    const float xlo = pxlo[0], xhi = pxhi[0];
    const float xblo = pxblo[0], xbhi = pxbhi[0];
    const float ylo = pylo[0], yhi = pyhi[0];

    // ---- prologue: initial state + static input segments ----
    {   // xf0 -> xp/xf state + scatter into all four input buffers
        int bm = tid >> 6, i = tid & 63;
        int p = bm >> 1, lane = bm & 1;
        float v = xf0[(b0 + bm) * NXF_ + i];
        int si = ((p * NXF_ + i) << 1) | lane;
        reinterpret_cast<float*>(sm.xf)[si] = v;
        reinterpret_cast<float*>(sm.xp)[si] = v;
        int ii = (((i << 2) | p) << 1) | lane;
        reinterpret_cast<float*>(sm.in_f )[ii] = v;
        reinterpret_cast<float*>(sm.in_fb)[ii] = v;
        reinterpret_cast<float*>(sm.in_h )[ii] = v;
        reinterpret_cast<float*>(sm.in_hb)[ii] = v;
    }
    if (tid < 256) {   // xb0 + mu/sig init + scatter
        int bm = tid >> 5, i = tid & 31;
        int p = bm >> 1, lane = bm & 1;
        float v = xb0[(b0 + bm) * NXB_ + i];
        int si = ((p * NXB_ + i) << 1) | lane;
        reinterpret_cast<float*>(sm.xb)[si]  = v;
        reinterpret_cast<float*>(sm.mu)[si]  = 0.0f;
        reinterpret_cast<float*>(sm.sig)[si] = 1.0f;
        int ii = ((((64 + i) << 2) | p) << 1) | lane;
        reinterpret_cast<float*>(sm.in_fb)[ii] = v;
        reinterpret_cast<float*>(sm.in_hb)[ii] = v;
    }
    if (tid < 64) {    // thetas
        int bm = tid >> 3, i = tid & 7;
        int p = bm >> 1, lane = bm & 1;
        reinterpret_cast<float*>(sm.in_f)[((((64 + NU_ + i) << 2) | p) << 1) | lane] =
            thfg[(b0 + bm) * NTH_ + i];
        reinterpret_cast<float*>(sm.in_h)[((((64 + i) << 2) | p) << 1) | lane] =
            thhg[(b0 + bm) * NTH_ + i];
    }
    __syncthreads();

    // store raw x row 0 + u_0 scatter (in_f/in_fb u slots)
    phaseE(sm, out, u, b0, 0, 0, tid, false, xlo, xhi, xblo, xbhi);
    __syncthreads();

    // D_init: h/hb hidden on initial state (feeds y_0 dots in B of t=0)
    phaseD(sm, tid, hW1, hbW1, hb1, hbb1);
    __syncthreads();

    // ---- main recurrence: iteration t computes state_{t+1}; stores y_t ----
    for (int t = 0; t < T_ - 1; t++) {
        const float tf = (float)t;

        // phase A: fused L1 of f + fb + gb, compact coalesced weights
        {
            const int j = tid;
            const float* wf = fW1 + j;
            const float* wb = fbW1 + j;
            const float* wg = gbW1 + j;
            const ulonglong2* inf = reinterpret_cast<const ulonglong2*>(sm.in_f);
            const ulonglong2* inb = reinterpret_cast<const ulonglong2*>(sm.in_fb);
            ull af0 = 0, af1 = 0, af2 = 0, af3 = 0;
            ull ab0 = 0, ab1 = 0, ab2 = 0, ab3 = 0;
            ull ag0 = 0, ag1 = 0, ag2 = 0, ag3 = 0;
#pragma unroll 2
            for (int k = 0; k < DIN_F; k++) {
                ull wwf = pack2(__ldg(wf)); wf += HID_;
                ull wwb = pack2(__ldg(wb)); wb += HID_;
                ull wwg = pack2(__ldg(wg)); wg += HID_;
                ulonglong2 fa = inf[2 * k], fc = inf[2 * k + 1];
                ulonglong2 ba = inb[2 * k], bc = inb[2 * k + 1];
                ffma2(af0, wwf, fa.x); ffma2(af1, wwf, fa.y);
                ffma2(af2, wwf, fc.x); ffma2(af3, wwf, fc.y);
                ffma2(ab0, wwb, ba.x); ffma2(ab1, wwb, ba.y);
                ffma2(ab2, wwb, bc.x); ffma2(ab3, wwb, bc.y);
                ffma2(ag0, wwg, ba.x); ffma2(ag1, wwg, ba.y);
                ffma2(ag2, wwg, bc.x); ffma2(ag3, wwg, bc.y);
            }
#pragma unroll 2
            for (int k = DIN_F; k < DIN_FB; k++) {
                ull wwb = pack2(__ldg(wb)); wb += HID_;
                ull wwg = pack2(__ldg(wg)); wg += HID_;
                ulonglong2 ba = inb[2 * k], bc = inb[2 * k + 1];
                ffma2(ab0, wwb, ba.x); ffma2(ab1, wwb, ba.y);
                ffma2(ab2, wwb, bc.x); ffma2(ab3, wwb, bc.y);
                ffma2(ag0, wwg, ba.x); ffma2(ag1, wwg, ba.y);
                ffma2(ag2, wwg, bc.x); ffma2(ag3, wwg, bc.y);
            }
            float bf = __ldg(fb1 + j), bb = __ldg(fbb1 + j), bg = __ldg(gbb1 + j);
            sm.hidf [0 * HID_ + j] = tanh2(af0, bf);
            sm.hidf [1 * HID_ + j] = tanh2(af1, bf);
            sm.hidf [2 * HID_ + j] = tanh2(af2, bf);
            sm.hidf [3 * HID_ + j] = tanh2(af3, bf);
            sm.hidfb[0 * HID_ + j] = tanh2(ab0, bb);
            sm.hidfb[1 * HID_ + j] = tanh2(ab1, bb);
            sm.hidfb[2 * HID_ + j] = tanh2(ab2, bb);
            sm.hidfb[3 * HID_ + j] = tanh2(ab3, bb);
            sm.hidgb[0 * HID_ + j] = tanh2(ag0, bg);
            sm.hidgb[1 * HID_ + j] = tanh2(ag1, bg);
            sm.hidgb[2 * HID_ + j] = tanh2(ag2, bg);
            sm.hidgb[3 * HID_ + j] = tanh2(ag3, bg);
        }
        __syncthreads();

        // phase B: all L2 dots — f+fb dual (256 thr), gb (128), y_t h/hb (128)
        if (tid < 256) {
            const int j = tid & 63, p = tid >> 6;
            const ulonglong2* hpF  = reinterpret_cast<const ulonglong2*>(
                sm.hidf  + p * HID_);
            const ulonglong2* hpFB = reinterpret_cast<const ulonglong2*>(
                sm.hidfb + p * HID_);
            float2 rF, rFB;
            dot512d_dual<NXF_, NXF_>(g_w2f, fb2_, hpF, j, rF,
                                     g_w2fb, fbb2, hpFB, j, rFB);
            sm.fo [p * NXF_ + j] = rF;
            sm.fbo[p * NXF_ + j] = rFB;
        } else if (tid < 384) {
            const int q = tid - 256, j = q & 31, p = q >> 5;
            const ulonglong2* hp = reinterpret_cast<const ulonglong2*>(
                sm.hidgb + p * HID_);
            sm.gbo[p * NXB_ + j] = dot512d<NXB_>(g_w2gb, gbb2, hp, j);
        } else if (tid < 448) {
            const int q = tid - 384, j = q & 15, p = q >> 4;
            const ulonglong2* hp = reinterpret_cast<const ulonglong2*>(
                sm.hidh + p * HID_);
            sm.yoh[p * NY_ + j] = dot512d<NY_>(g_w2h, hb2_, hp, j);
        } else {
            const int q = tid - 448, j = q & 15, p = q >> 4;
            const ulonglong2* hp = reinterpret_cast<const ulonglong2*>(
                sm.hidhb + p * HID_);
            sm.yohb[p * NY_ + j] = dot512d<NY_>(g_w2hb, hbb2, hp, j);
        }
        __syncthreads();

        // phase C: gate + state update + pre-clip scatter | y_t store
        if (tid < 128) {
            int q = tid, p = q >> 5, i = q & 31;
            float2 xb2 = sm.xb[q], mu2 = sm.mu[q], sg2 = sm.sig[q], gb2 = sm.gbo[q];
            float xbn, mun, sgn;
            gate_update(xb2.x, mu2.x, sg2.x, gb2.x, tf + 1.0f, tf + 2.0f,
                        xblo, xbhi, xbn, mun, sgn);
            xb2.x = xbn; mu2.x = mun; sg2.x = sgn;
            gate_update(xb2.y, mu2.y, sg2.y, gb2.y, tf + 1.0f, tf + 2.0f,
                        xblo, xbhi, xbn, mun, sgn);
            xb2.y = xbn; mu2.y = mun; sg2.y = sgn;
            sm.xb[q] = xb2; sm.mu[q] = mu2; sm.sig[q] = sg2;
            sm.in_hb[((64 + i) << 2) | p] = xb2;        // pre-clip xb_{t+1}
        } else if (tid < 384) {
            int q = tid - 128, p = q >> 6, i = q & 63;
            float2 xp2 = sm.xp[q], xf2 = sm.xf[q], f2 = sm.fo[q], fb2 = sm.fbo[q];
            float dfx = f2.x + fb2.x, dfy = f2.y + fb2.y;
            float2 xpn = make_float2(xp2.x + f2.x, xp2.y + f2.y);
            float2 xfn = make_float2(xf2.x + dfx, xf2.y + dfy);
            sm.xp[q] = xpn; sm.xf[q] = xfn;
            sm.in_h [(i << 2) | p] = xpn;               // pre-clip xp_{t+1}
            sm.in_hb[(i << 2) | p] = xfn;               // pre-clip xf_{t+1}
        } else {
            // store y row t (raw for t=0, clipped otherwise)
            int e = tid - 384;
            int bm = e >> 4, i = e & 15;
            int si = (((bm >> 1) * NY_ + i) << 1) | (bm & 1);
            float v = reinterpret_cast<float*>(sm.yoh)[si]
                    + reinterpret_cast<float*>(sm.yohb)[si];
            if (t > 0) v = clipf(v, ylo, yhi);
            out[OFF_Y + ((size_t)(b0 + bm) * T_ + t) * NY_ + i] = v;
        }
        __syncthreads();

        // phase D: h/hb L1 on pre-clip state_{t+1} (feeds y_{t+1} in next B)
        phaseD(sm, tid, hW1, hbW1, hb1, hbb1);
        __syncthreads();

        // phase E: clip + store x row t+1 + scatter clipped + u_{t+1} prefetch
        phaseE(sm, out, u, b0, t + 1, t + 1, tid, true, xlo, xhi, xblo, xbhi);
        __syncthreads();
    }

    // ---- epilogue: y row 255 from the last D's hidden activations ----
    if (tid < 128) {
        const bool isH = tid < 64;
        const int q = isH ? tid : tid - 64;
        const int j = q & 15, p = q >> 4;
        const ulonglong2* hp = reinterpret_cast<const ulonglong2*>(
            (isH ? sm.hidh : sm.hidhb) + p * HID_);
        float2 r = dot512d<NY_>(isH ? g_w2h : g_w2hb, isH ? hb2_ : hbb2, hp, j);
        (isH ? sm.yoh : sm.yohb)[p * NY_ + j] = r;
    }
    __syncthreads();
    if (tid < 128) {
        int bm = tid >> 4, i = tid & 15;
        int si = (((bm >> 1) * NY_ + i) << 1) | (bm & 1);
        float v = reinterpret_cast<float*>(sm.yoh)[si]
                + reinterpret_cast<float*>(sm.yohb)[si];
        v = clipf(v, ylo, yhi);
        out[OFF_Y + ((size_t)(b0 + bm) * T_ + (T_ - 1)) * NY_ + i] = v;
    }
}

// ---------------------------------------------------------------------------
extern "C" void kernel_launch(void* const* d_in, const int* in_sizes, int n_in,
                              void* d_out, int out_size) {
    (void)in_sizes; (void)n_in; (void)out_size;
    const float* xf0  = (const float*)d_in[0];
    const float* xb0  = (const float*)d_in[1];
    const float* uu   = (const float*)d_in[2];
    const float* thf  = (const float*)d_in[3];
    const float* thh  = (const float*)d_in[4];
    const float* fW1  = (const float*)d_in[5];
    const float* fb1  = (const float*)d_in[6];
    const float* fW2  = (const float*)d_in[7];
    const float* fb2  = (const float*)d_in[8];
    const float* fbW1 = (const float*)d_in[9];
    const float* fbb1 = (const float*)d_in[10];
    const float* fbW2 = (const float*)d_in[11];
    const float* fbb2 = (const float*)d_in[12];
    const float* gbW1 = (const float*)d_in[13];
    const float* gbb1 = (const float*)d_in[14];
    const float* gbW2 = (const float*)d_in[15];
    const float* gbb2 = (const float*)d_in[16];
    const float* hW1  = (const float*)d_in[17];
    const float* hb1  = (const float*)d_in[18];
    const float* hW2  = (const float*)d_in[19];
    const float* hb2  = (const float*)d_in[20];
    const float* hbW1 = (const float*)d_in[21];
    const float* hbb1 = (const float*)d_in[22];
    const float* hbW2 = (const float*)d_in[23];
    const float* hbb2 = (const float*)d_in[24];
    const float* xlo  = (const float*)d_in[25];
    const float* xhi  = (const float*)d_in[26];
    const float* xblo = (const float*)d_in[27];
    const float* xbhi = (const float*)d_in[28];
    const float* ylo  = (const float*)d_in[29];
    const float* yhi  = (const float*)d_in[30];

    // duplicate W2 into f32x2 scratch (deterministic, graph-capturable)
    prep_kernel<<<(HID_ * NXF_ + 511) / 512, 512>>>(fW2, fbW2, gbW2, hW2, hbW2);

    cudaFuncSetAttribute(sim_kernel,
                         cudaFuncAttributeMaxDynamicSharedMemorySize,
                         (int)sizeof(SmemX));
    sim_kernel<<<B_ / BM, NT, sizeof(SmemX)>>>(
        xf0, xb0, uu, thf, thh,
        fW1, fb1, fbW1, fbb1, gbW1, gbb1, hW1, hb1, hbW1, hbb1,
        fb2, fbb2, gbb2, hb2, hbb2,
        xlo, xhi, xblo, xbhi, ylo, yhi,
        (float*)d_out);
}

// round 11
// speedup vs baseline: 1.7037x; 1.2395x over previous
#include <cuda_runtime.h>

// ---------------------------------------------------------------------------
// RobustStateSpaceSimulatorAugmented: B=1024 rows, T=256 sequential steps.
// 128 CTAs x 512 threads, 8 rows per CTA, rows packed in pairs into f32x2.
//
// Numerics FROZEN: XLA EmitFastTanh, each dot = single ascending-k fp32x2 FMA
// chain, bias after dot, gate math op-for-op.
// R10: phase-B L2 dots use weight-SHARED dual chains (thread (j,pg) computes
// outputs (j,2pg),(j,2pg+1) off one compact scalar weight stream) — 2.5x fewer
// L1 wavefronts, half the B weight traffic. Prep kernel / dup-W2 removed.
// ---------------------------------------------------------------------------

namespace {
constexpr int B_  = 1024;
constexpr int T_  = 256;
constexpr int NXF_ = 64;
constexpr int NXB_ = 32;
constexpr int NU_  = 16;
constexpr int NY_  = 16;
constexpr int NTH_ = 8;
constexpr int HID_ = 512;

constexpr int BM = 8;
constexpr int P  = BM / 2;
constexpr int NT = 512;

constexpr int DIN_F  = NXF_ + NU_  + NTH_;  // 88
constexpr int DIN_FB = NXF_ + NXB_ + NU_;   // 112
constexpr int DIN_H  = NXF_ + NTH_;         // 72
constexpr int DIN_HB = NXF_ + NXB_;         // 96

constexpr long OFF_XF = 0;
constexpr long OFF_XB = OFF_XF + (long)B_ * T_ * NXF_;
constexpr long OFF_Y  = OFF_XB + (long)B_ * T_ * NXB_;
constexpr long OFF_XP = OFF_Y  + (long)B_ * T_ * NY_;
} // namespace

typedef unsigned long long ull;

// ---------------------------------------------------------------------------
// f32x2 helpers
// ---------------------------------------------------------------------------
__device__ __forceinline__ ull pack2(float w) {
    ull r;
    asm("mov.b64 %0, {%1, %1};" : "=l"(r) : "f"(w));
    return r;
}

__device__ __forceinline__ float2 unpack2(ull v) {
    float2 r;
    asm("mov.b64 {%0, %1}, %2;" : "=f"(r.x), "=f"(r.y) : "l"(v));
    return r;
}

__device__ __forceinline__ void ffma2(ull& acc, ull a, ull b) {
    asm("fma.rn.f32x2 %0, %1, %2, %0;" : "+l"(acc) : "l"(a), "l"(b));
}

__device__ __forceinline__ float clipf(float v, float lo, float hi) {
    return fminf(fmaxf(v, lo), hi);
}

// XLA f32 tanh (EmitFastTanh / Eigen ptanh) — numerics frozen
__device__ __forceinline__ float xla_tanh(float x) {
    const float kMax = 7.90531110763549805f;
    float xc = fminf(fmaxf(x, -kMax), kMax);
    float x2 = xc * xc;
    float n = -2.76076847742355e-16f;
    n = fmaf(x2, n,  2.00018790482477e-13f);
    n = fmaf(x2, n, -8.60467152213735e-11f);
    n = fmaf(x2, n,  5.12229709037114e-08f);
    n = fmaf(x2, n,  1.48572235717979e-05f);
    n = fmaf(x2, n,  6.37261928875436e-04f);
    n = fmaf(x2, n,  4.89352455891786e-03f);
    n = xc * n;
    float d = 1.19825839466702e-06f;
    d = fmaf(x2, d, 1.18534705686654e-04f);
    d = fmaf(x2, d, 2.26843463243900e-03f);
    d = fmaf(x2, d, 4.89352518554385e-03f);
    float r = n / d;
    return fabsf(x) < 0.0004f ? x : r;
}

__device__ __forceinline__ float2 tanh2(ull acc, float bb) {
    float2 v = unpack2(acc);
    return make_float2(xla_tanh(v.x + bb), xla_tanh(v.y + bb));
}

// ---------------------------------------------------------------------------
// shared memory (~107 KB, 1 CTA/SM)
// ---------------------------------------------------------------------------
struct __align__(16) SmemX {
    float2 in_f [DIN_F  * P];  // [0,64) xp | [64,80) u | [80,88) thf
    float2 in_fb[DIN_FB * P];  // [0,64) xp | [64,96) xb | [96,112) u
    float2 in_h [DIN_H  * P];  // [0,64) xp | [64,72) thh
    float2 in_hb[DIN_HB * P];  // [0,64) xf | [64,96) xb   (PRE-clip)
    float2 hidf [P * HID_];
    float2 hidfb[P * HID_];
    float2 hidgb[P * HID_];
    float2 hidh [P * HID_];
    float2 hidhb[P * HID_];
    float2 xp[P * NXF_], xf[P * NXF_];
    float2 xb[P * NXB_], mu[P * NXB_], sig[P * NXB_];
    float2 fo[P * NXF_], fbo[P * NXF_], gbo[P * NXB_];
    float2 yoh[P * NY_], yohb[P * NY_];
};

// ---------------------------------------------------------------------------
// L2 dots, compact scalar weights. Each output chain is the exact ascending-k
// sequence  ffma2(acc, w[2k2], h.x); ffma2(acc, w[2k2+1], h.y)  — frozen.
// ---------------------------------------------------------------------------

// one weight stream feeding TWO independent chains (outputs (j,p0),(j,p1))
template <int DOUT>
__device__ __forceinline__ void dot512_2p(const float* __restrict__ W2,
                                          const float* __restrict__ b2, int j,
                                          const ulonglong2* __restrict__ hp0,
                                          const ulonglong2* __restrict__ hp1,
                                          float2& o0, float2& o1) {
    const float* w = W2 + j;
    ull a0 = 0ull, a1 = 0ull;
#pragma unroll 4
    for (int k2 = 0; k2 < HID_ / 2; k2++) {
        ull w0 = pack2(__ldg(w)); w += DOUT;
        ull w1 = pack2(__ldg(w)); w += DOUT;
        ulonglong2 h0 = hp0[k2], h1 = hp1[k2];
        ffma2(a0, w0, h0.x); ffma2(a0, w1, h0.y);
        ffma2(a1, w0, h1.x); ffma2(a1, w1, h1.y);
    }
    float bb = __ldg(b2 + j);
    o0 = unpack2(a0); o0.x += bb; o0.y += bb;
    o1 = unpack2(a1); o1.x += bb; o1.y += bb;
}

// single chain (epilogue only)
template <int DOUT>
__device__ __forceinline__ float2 dot512c(const float* __restrict__ W2,
                                          const float* __restrict__ b2, int j,
                                          const ulonglong2* __restrict__ hp2) {
    const float* w = W2 + j;
    ull acc = 0ull;
#pragma unroll 4
    for (int k2 = 0; k2 < HID_ / 2; k2++) {
        ull w0 = pack2(__ldg(w)); w += DOUT;
        ull w1 = pack2(__ldg(w)); w += DOUT;
        ulonglong2 h = hp2[k2];
        ffma2(acc, w0, h.x);
        ffma2(acc, w1, h.y);
    }
    float2 s = unpack2(acc);
    float bb = __ldg(b2 + j);
    s.x += bb; s.y += bb;
    return s;
}

// gating + mu/sigma (op-for-op vs reference; numerics frozen)
__device__ __forceinline__ void gate_update(float xb, float mu, float sig, float gbv,
                                            float t1, float t2, float xblo, float xbhi,
                                            float& xbn, float& mun, float& sgn) {
    float inv_gp  = 1.0f / sig;
    float inv_gp2 = 1.0f / (sig * sig);
    float xmmu = xb - mu;
    float delta1 = gbv * (xmmu + (gbv * 0.5f) * (1.0f + inv_gp));
    float delta2 = 1.0f - inv_gp;
    float delta = delta1 * delta2;
    float eps = t2 * (sig * sig - t2 / t1)
              + xmmu * (xmmu + gbv * (1.0f + inv_gp)
                        + (gbv * gbv * 0.5f) * (1.0f + inv_gp2));
    float d2e2 = delta * delta - eps * eps;
    bool c = ((eps >= delta) && (delta >= 0.0f))
          || ((eps <  delta) && (delta <  0.0f))
          || ((delta < eps)  && (eps  <  0.0f))
          || (((2.0f * t2 * t2 / t1) * eps >= d2e2) && (d2e2 > 0.0f));
    float gamma = c ? sig : 1.0f;
    float dxb = gbv / gamma;
    xbn = dxb;
    float xbc = fminf(fmaxf(dxb, xblo), xbhi);
    float c1 = t1 / t2;
    float c2 = 1.0f / t2;
    mun = c1 * mu + c2 * xbc;
    float dm = xbc - mun;
    sgn = sqrtf(c1 * (sig * sig) + c2 * (dm * dm));
}

// ---------------------------------------------------------------------------
// phase D: fused h/hb L1, compact coalesced scalar weight loads
// ---------------------------------------------------------------------------
__device__ __forceinline__ void phaseD(SmemX& sm, int tid,
                                       const float* __restrict__ hW1,
                                       const float* __restrict__ hbW1,
                                       const float* __restrict__ hb1,
                                       const float* __restrict__ hbb1) {
    const int j = tid;
    const float* wh = hW1 + j;
    const float* wb = hbW1 + j;
    const ulonglong2* inh = reinterpret_cast<const ulonglong2*>(sm.in_h);
    const ulonglong2* inb = reinterpret_cast<const ulonglong2*>(sm.in_hb);
    ull ah0 = 0, ah1 = 0, ah2 = 0, ah3 = 0;
    ull ab0 = 0, ab1 = 0, ab2 = 0, ab3 = 0;
#pragma unroll 2
    for (int k = 0; k < DIN_H; k++) {
        ull wwh = pack2(__ldg(wh)); wh += HID_;
        ull wwb = pack2(__ldg(wb)); wb += HID_;
        ulonglong2 ha = inh[2 * k], hc = inh[2 * k + 1];
        ulonglong2 ba = inb[2 * k], bc = inb[2 * k + 1];
        ffma2(ah0, wwh, ha.x); ffma2(ah1, wwh, ha.y);
        ffma2(ah2, wwh, hc.x); ffma2(ah3, wwh, hc.y);
        ffma2(ab0, wwb, ba.x); ffma2(ab1, wwb, ba.y);
        ffma2(ab2, wwb, bc.x); ffma2(ab3, wwb, bc.y);
    }
#pragma unroll 4
    for (int k = DIN_H; k < DIN_HB; k++) {
        ull wwb = pack2(__ldg(wb)); wb += HID_;
        ulonglong2 ba = inb[2 * k], bc = inb[2 * k + 1];
        ffma2(ab0, wwb, ba.x); ffma2(ab1, wwb, ba.y);
        ffma2(ab2, wwb, bc.x); ffma2(ab3, wwb, bc.y);
    }
    float bh = __ldg(hb1 + j), bb = __ldg(hbb1 + j);
    sm.hidh [0 * HID_ + j] = tanh2(ah0, bh);
    sm.hidh [1 * HID_ + j] = tanh2(ah1, bh);
    sm.hidh [2 * HID_ + j] = tanh2(ah2, bh);
    sm.hidh [3 * HID_ + j] = tanh2(ah3, bh);
    sm.hidhb[0 * HID_ + j] = tanh2(ab0, bb);
    sm.hidhb[1 * HID_ + j] = tanh2(ab1, bb);
    sm.hidhb[2 * HID_ + j] = tanh2(ab2, bb);
    sm.hidhb[3 * HID_ + j] = tanh2(ab3, bb);
}

// ---------------------------------------------------------------------------
// phase E: x stores (+clip, + scatter clipped into in_f/in_fb) + u prefetch
// ---------------------------------------------------------------------------
__device__ __forceinline__ void phaseE(SmemX& sm, float* __restrict__ out,
                                       const float* __restrict__ u, int b0,
                                       int ti, int t_next, int tid, bool doclip,
                                       float xlo, float xhi, float xblo, float xbhi) {
    if (tid < 256) {
#pragma unroll
        for (int r = 0; r < 2; r++) {
            int e = (tid << 1) | r;
            int bm = e >> 6, i = e & 63;
            int p = bm >> 1, lane = bm & 1;
            int si = ((p * NXF_ + i) << 1) | lane;
            float vf = reinterpret_cast<float*>(sm.xf)[si];
            float vp = reinterpret_cast<float*>(sm.xp)[si];
            if (doclip) {
                vf = clipf(vf, xlo, xhi); vp = clipf(vp, xlo, xhi);
                reinterpret_cast<float*>(sm.xf)[si] = vf;
                reinterpret_cast<float*>(sm.xp)[si] = vp;
            }
            size_t base = ((size_t)(b0 + bm) * T_ + ti);
            out[OFF_XF + base * NXF_ + i] = vf;
            out[OFF_XP + base * NXF_ + i] = vp;
            reinterpret_cast<float*>(sm.in_f )[(((i << 2) | p) << 1) | lane] = vp;
            reinterpret_cast<float*>(sm.in_fb)[(((i << 2) | p) << 1) | lane] = vp;
        }
    } else if (tid < 384) {
#pragma unroll
        for (int r = 0; r < 2; r++) {
            int e = (((tid - 256) << 1) | r);
            int bm = e >> 5, i = e & 31;
            int p = bm >> 1, lane = bm & 1;
            int si = ((p * NXB_ + i) << 1) | lane;
            float v = reinterpret_cast<float*>(sm.xb)[si];
            if (doclip) { v = clipf(v, xblo, xbhi);
                          reinterpret_cast<float*>(sm.xb)[si] = v; }
            out[OFF_XB + ((size_t)(b0 + bm) * T_ + ti) * NXB_ + i] = v;
            reinterpret_cast<float*>(sm.in_fb)[((((64 + i) << 2) | p) << 1) | lane] = v;
        }
    } else {   // u[:, t_next, :] into in_f [64,80) and in_fb [96,112)
        int e = tid - 384;
        int bm = e >> 4, i = e & 15;
        int p = bm >> 1, lane = bm & 1;
        float v = u[((size_t)(b0 + bm) * T_ + t_next) * NU_ + i];
        reinterpret_cast<float*>(sm.in_f )[((((64 + i) << 2) | p) << 1) | lane] = v;
        reinterpret_cast<float*>(sm.in_fb)[((((96 + i) << 2) | p) << 1) | lane] = v;
    }
}

// ---------------------------------------------------------------------------
// main persistent kernel
// ---------------------------------------------------------------------------
__global__ void __launch_bounds__(NT, 1)
sim_kernel(const float* __restrict__ xf0, const float* __restrict__ xb0,
           const float* __restrict__ u,   const float* __restrict__ thfg,
           const float* __restrict__ thhg,
           const float* __restrict__ fW1,  const float* __restrict__ fb1,
           const float* __restrict__ fbW1, const float* __restrict__ fbb1,
           const float* __restrict__ gbW1, const float* __restrict__ gbb1,
           const float* __restrict__ hW1,  const float* __restrict__ hb1,
           const float* __restrict__ hbW1, const float* __restrict__ hbb1,
           const float* __restrict__ fW2,  const float* __restrict__ fb2_,
           const float* __restrict__ fbW2, const float* __restrict__ fbb2,
           const float* __restrict__ gbW2, const float* __restrict__ gbb2,
           const float* __restrict__ hW2,  const float* __restrict__ hb2_,
           const float* __restrict__ hbW2, const float* __restrict__ hbb2,
           const float* __restrict__ pxlo, const float* __restrict__ pxhi,
           const float* __restrict__ pxblo,const float* __restrict__ pxbhi,
           const float* __restrict__ pylo, const float* __restrict__ pyhi,
           float* __restrict__ out) {
    extern __shared__ __align__(16) char dynraw[];
    SmemX& sm = *reinterpret_cast<SmemX*>(dynraw);

    const int tid = threadIdx.x;
    const int b0  = blockIdx.x * BM;
    const float xlo = pxlo[0], xhi = pxhi[0];
    const float xblo = pxblo[0], xbhi = pxbhi[0];
    const float ylo = pylo[0], yhi = pyhi[0];

    // ---- prologue: initial state + static input segments ----
    {   // xf0 -> xp/xf state + scatter into all four input buffers
        int bm = tid >> 6, i = tid & 63;
        int p = bm >> 1, lane = bm & 1;
        float v = xf0[(b0 + bm) * NXF_ + i];
        int si = ((p * NXF_ + i) << 1) | lane;
        reinterpret_cast<float*>(sm.xf)[si] = v;
        reinterpret_cast<float*>(sm.xp)[si] = v;
        int ii = (((i << 2) | p) << 1) | lane;
        reinterpret_cast<float*>(sm.in_f )[ii] = v;
        reinterpret_cast<float*>(sm.in_fb)[ii] = v;
        reinterpret_cast<float*>(sm.in_h )[ii] = v;
        reinterpret_cast<float*>(sm.in_hb)[ii] = v;
    }
    if (tid < 256) {   // xb0 + mu/sig init + scatter
        int bm = tid >> 5, i = tid & 31;
        int p = bm >> 1, lane = bm & 1;
        float v = xb0[(b0 + bm) * NXB_ + i];
        int si = ((p * NXB_ + i) << 1) | lane;
        reinterpret_cast<float*>(sm.xb)[si]  = v;
        reinterpret_cast<float*>(sm.mu)[si]  = 0.0f;
        reinterpret_cast<float*>(sm.sig)[si] = 1.0f;
        int ii = ((((64 + i) << 2) | p) << 1) | lane;
        reinterpret_cast<float*>(sm.in_fb)[ii] = v;
        reinterpret_cast<float*>(sm.in_hb)[ii] = v;
    }
    if (tid < 64) {    // thetas
        int bm = tid >> 3, i = tid & 7;
        int p = bm >> 1, lane = bm & 1;
        reinterpret_cast<float*>(sm.in_f)[((((64 + NU_ + i) << 2) | p) << 1) | lane] =
            thfg[(b0 + bm) * NTH_ + i];
        reinterpret_cast<float*>(sm.in_h)[((((64 + i) << 2) | p) << 1) | lane] =
            thhg[(b0 + bm) * NTH_ + i];
    }
    __syncthreads();

    // store raw x row 0 + u_0 scatter (in_f/in_fb u slots)
    phaseE(sm, out, u, b0, 0, 0, tid, false, xlo, xhi, xblo, xbhi);
    __syncthreads();

    // D_init: h/hb hidden on initial state (feeds y_0 dots in B of t=0)
    phaseD(sm, tid, hW1, hbW1, hb1, hbb1);
    __syncthreads();

    // ---- main recurrence: iteration t computes state_{t+1}; stores y_t ----
    for (int t = 0; t < T_ - 1; t++) {
        const float tf = (float)t;

        // phase A: fused L1 of f + fb + gb, compact coalesced weights
        {
            const int j = tid;
            const float* wf = fW1 + j;
            const float* wb = fbW1 + j;
            const float* wg = gbW1 + j;
            const ulonglong2* inf = reinterpret_cast<const ulonglong2*>(sm.in_f);
            const ulonglong2* inb = reinterpret_cast<const ulonglong2*>(sm.in_fb);
            ull af0 = 0, af1 = 0, af2 = 0, af3 = 0;
            ull ab0 = 0, ab1 = 0, ab2 = 0, ab3 = 0;
            ull ag0 = 0, ag1 = 0, ag2 = 0, ag3 = 0;
#pragma unroll 2
            for (int k = 0; k < DIN_F; k++) {
                ull wwf = pack2(__ldg(wf)); wf += HID_;
                ull wwb = pack2(__ldg(wb)); wb += HID_;
                ull wwg = pack2(__ldg(wg)); wg += HID_;
                ulonglong2 fa = inf[2 * k], fc = inf[2 * k + 1];
                ulonglong2 ba = inb[2 * k], bc = inb[2 * k + 1];
                ffma2(af0, wwf, fa.x); ffma2(af1, wwf, fa.y);
                ffma2(af2, wwf, fc.x); ffma2(af3, wwf, fc.y);
                ffma2(ab0, wwb, ba.x); ffma2(ab1, wwb, ba.y);
                ffma2(ab2, wwb, bc.x); ffma2(ab3, wwb, bc.y);
                ffma2(ag0, wwg, ba.x); ffma2(ag1, wwg, ba.y);
                ffma2(ag2, wwg, bc.x); ffma2(ag3, wwg, bc.y);
            }
#pragma unroll 2
            for (int k = DIN_F; k < DIN_FB; k++) {
                ull wwb = pack2(__ldg(wb)); wb += HID_;
                ull wwg = pack2(__ldg(wg)); wg += HID_;
                ulonglong2 ba = inb[2 * k], bc = inb[2 * k + 1];
                ffma2(ab0, wwb, ba.x); ffma2(ab1, wwb, ba.y);
                ffma2(ab2, wwb, bc.x); ffma2(ab3, wwb, bc.y);
                ffma2(ag0, wwg, ba.x); ffma2(ag1, wwg, ba.y);
                ffma2(ag2, wwg, bc.x); ffma2(ag3, wwg, bc.y);
            }
            float bf = __ldg(fb1 + j), bb = __ldg(fbb1 + j), bg = __ldg(gbb1 + j);
            sm.hidf [0 * HID_ + j] = tanh2(af0, bf);
            sm.hidf [1 * HID_ + j] = tanh2(af1, bf);
            sm.hidf [2 * HID_ + j] = tanh2(af2, bf);
            sm.hidf [3 * HID_ + j] = tanh2(af3, bf);
            sm.hidfb[0 * HID_ + j] = tanh2(ab0, bb);
            sm.hidfb[1 * HID_ + j] = tanh2(ab1, bb);
            sm.hidfb[2 * HID_ + j] = tanh2(ab2, bb);
            sm.hidfb[3 * HID_ + j] = tanh2(ab3, bb);
            sm.hidgb[0 * HID_ + j] = tanh2(ag0, bg);
            sm.hidgb[1 * HID_ + j] = tanh2(ag1, bg);
            sm.hidgb[2 * HID_ + j] = tanh2(ag2, bg);
            sm.hidgb[3 * HID_ + j] = tanh2(ag3, bg);
        }
        __syncthreads();

        // phase B: weight-shared dual-chain L2 dots (384 active threads)
        //   f: 0-127 | fb: 128-255 | gb: 256-319 | h: 320-351 | hb: 352-383
        if (tid < 128) {
            const int j = tid & 63, pg = tid >> 6;
            const ulonglong2* hp0 = reinterpret_cast<const ulonglong2*>(
                sm.hidf + (2 * pg) * HID_);
            const ulonglong2* hp1 = reinterpret_cast<const ulonglong2*>(
                sm.hidf + (2 * pg + 1) * HID_);
            float2 o0, o1;
            dot512_2p<NXF_>(fW2, fb2_, j, hp0, hp1, o0, o1);
            sm.fo[(2 * pg) * NXF_ + j]     = o0;
            sm.fo[(2 * pg + 1) * NXF_ + j] = o1;
        } else if (tid < 256) {
            const int q = tid - 128, j = q & 63, pg = q >> 6;
            const ulonglong2* hp0 = reinterpret_cast<const ulonglong2*>(
                sm.hidfb + (2 * pg) * HID_);
            const ulonglong2* hp1 = reinterpret_cast<const ulonglong2*>(
                sm.hidfb + (2 * pg + 1) * HID_);
            float2 o0, o1;
            dot512_2p<NXF_>(fbW2, fbb2, j, hp0, hp1, o0, o1);
            sm.fbo[(2 * pg) * NXF_ + j]     = o0;
            sm.fbo[(2 * pg + 1) * NXF_ + j] = o1;
        } else if (tid < 320) {
            const int q = tid - 256, j = q & 31, pg = q >> 5;
            const ulonglong2* hp0 = reinterpret_cast<const ulonglong2*>(
                sm.hidgb + (2 * pg) * HID_);
            const ulonglong2* hp1 = reinterpret_cast<const ulonglong2*>(
                sm.hidgb + (2 * pg + 1) * HID_);
            float2 o0, o1;
            dot512_2p<NXB_>(gbW2, gbb2, j, hp0, hp1, o0, o1);
            sm.gbo[(2 * pg) * NXB_ + j]     = o0;
            sm.gbo[(2 * pg + 1) * NXB_ + j] = o1;
        } else if (tid < 352) {
            const int q = tid - 320, j = q & 15, pg = q >> 4;
            const ulonglong2* hp0 = reinterpret_cast<const ulonglong2*>(
                sm.hidh + (2 * pg) * HID_);
            const ulonglong2* hp1 = reinterpret_cast<const ulonglong2*>(
                sm.hidh + (2 * pg + 1) * HID_);
            float2 o0, o1;
            dot512_2p<NY_>(hW2, hb2_, j, hp0, hp1, o0, o1);
            sm.yoh[(2 * pg) * NY_ + j]     = o0;
            sm.yoh[(2 * pg + 1) * NY_ + j] = o1;
        } else if (tid < 384) {
            const int q = tid - 352, j = q & 15, pg = q >> 4;
            const ulonglong2* hp0 = reinterpret_cast<const ulonglong2*>(
                sm.hidhb + (2 * pg) * HID_);
            const ulonglong2* hp1 = reinterpret_cast<const ulonglong2*>(
                sm.hidhb + (2 * pg + 1) * HID_);
            float2 o0, o1;
            dot512_2p<NY_>(hbW2, hbb2, j, hp0, hp1, o0, o1);
            sm.yohb[(2 * pg) * NY_ + j]     = o0;
            sm.yohb[(2 * pg + 1) * NY_ + j] = o1;
        }
        __syncthreads();

        // phase C: gate + state update + pre-clip scatter | y_t store
        if (tid < 128) {
            int q = tid, p = q >> 5, i = q & 31;
            float2 xb2 = sm.xb[q], mu2 = sm.mu[q], sg2 = sm.sig[q], gb2 = sm.gbo[q];
            float xbn, mun, sgn;
            gate_update(xb2.x, mu2.x, sg2.x, gb2.x, tf + 1.0f, tf + 2.0f,
                        xblo, xbhi, xbn, mun, sgn);
            xb2.x = xbn; mu2.x = mun; sg2.x = sgn;
            gate_update(xb2.y, mu2.y, sg2.y, gb2.y, tf + 1.0f, tf + 2.0f,
                        xblo, xbhi, xbn, mun, sgn);
            xb2.y = xbn; mu2.y = mun; sg2.y = sgn;
            sm.xb[q] = xb2; sm.mu[q] = mu2; sm.sig[q] = sg2;
            sm.in_hb[((64 + i) << 2) | p] = xb2;        // pre-clip xb_{t+1}
        } else if (tid < 384) {
            int q = tid - 128, p = q >> 6, i = q & 63;
            float2 xp2 = sm.xp[q], xf2 = sm.xf[q], f2 = sm.fo[q], fb2 = sm.fbo[q];
            float dfx = f2.x + fb2.x, dfy = f2.y + fb2.y;
            float2 xpn = make_float2(xp2.x + f2.x, xp2.y + f2.y);
            float2 xfn = make_float2(xf2.x + dfx, xf2.y + dfy);
            sm.xp[q] = xpn; sm.xf[q] = xfn;
            sm.in_h [(i << 2) | p] = xpn;               // pre-clip xp_{t+1}
            sm.in_hb[(i << 2) | p] = xfn;               // pre-clip xf_{t+1}
        } else {
            // store y row t (raw for t=0, clipped otherwise)
            int e = tid - 384;
            int bm = e >> 4, i = e & 15;
            int si = (((bm >> 1) * NY_ + i) << 1) | (bm & 1);
            float v = reinterpret_cast<float*>(sm.yoh)[si]
                    + reinterpret_cast<float*>(sm.yohb)[si];
            if (t > 0) v = clipf(v, ylo, yhi);
            out[OFF_Y + ((size_t)(b0 + bm) * T_ + t) * NY_ + i] = v;
        }
        __syncthreads();

        // phase D: h/hb L1 on pre-clip state_{t+1} (feeds y_{t+1} in next B)
        phaseD(sm, tid, hW1, hbW1, hb1, hbb1);
        __syncthreads();

        // phase E: clip + store x row t+1 + scatter clipped + u_{t+1} prefetch
        phaseE(sm, out, u, b0, t + 1, t + 1, tid, true, xlo, xhi, xblo, xbhi);
        __syncthreads();
    }

    // ---- epilogue: y row 255 from the last D's hidden activations ----
    if (tid < 128) {
        const bool isH = tid < 64;
        const int q = isH ? tid : tid - 64;
        const int j = q & 15, p = q >> 4;
        const ulonglong2* hp = reinterpret_cast<const ulonglong2*>(
            (isH ? sm.hidh : sm.hidhb) + p * HID_);
        float2 r = dot512c<NY_>(isH ? hW2 : hbW2, isH ? hb2_ : hbb2, j, hp);
        (isH ? sm.yoh : sm.yohb)[p * NY_ + j] = r;
    }
    __syncthreads();
    if (tid < 128) {
        int bm = tid >> 4, i = tid & 15;
        int si = (((bm >> 1) * NY_ + i) << 1) | (bm & 1);
        float v = reinterpret_cast<float*>(sm.yoh)[si]
                + reinterpret_cast<float*>(sm.yohb)[si];
        v = clipf(v, ylo, yhi);
        out[OFF_Y + ((size_t)(b0 + bm) * T_ + (T_ - 1)) * NY_ + i] = v;
    }
}

// ---------------------------------------------------------------------------
extern "C" void kernel_launch(void* const* d_in, const int* in_sizes, int n_in,
                              void* d_out, int out_size) {
    (void)in_sizes; (void)n_in; (void)out_size;
    const float* xf0  = (const float*)d_in[0];
    const float* xb0  = (const float*)d_in[1];
    const float* uu   = (const float*)d_in[2];
    const float* thf  = (const float*)d_in[3];
    const float* thh  = (const float*)d_in[4];
    const float* fW1  = (const float*)d_in[5];
    const float* fb1  = (const float*)d_in[6];
    const float* fW2  = (const float*)d_in[7];
    const float* fb2  = (const float*)d_in[8];
    const float* fbW1 = (const float*)d_in[9];
    const float* fbb1 = (const float*)d_in[10];
    const float* fbW2 = (const float*)d_in[11];
    const float* fbb2 = (const float*)d_in[12];
    const float* gbW1 = (const float*)d_in[13];
    const float* gbb1 = (const float*)d_in[14];
    const float* gbW2 = (const float*)d_in[15];
    const float* gbb2 = (const float*)d_in[16];
    const float* hW1  = (const float*)d_in[17];
    const float* hb1  = (const float*)d_in[18];
    const float* hW2  = (const float*)d_in[19];
    const float* hb2  = (const float*)d_in[20];
    const float* hbW1 = (const float*)d_in[21];
    const float* hbb1 = (const float*)d_in[22];
    const float* hbW2 = (const float*)d_in[23];
    const float* hbb2 = (const float*)d_in[24];
    const float* xlo  = (const float*)d_in[25];
    const float* xhi  = (const float*)d_in[26];
    const float* xblo = (const float*)d_in[27];
    const float* xbhi = (const float*)d_in[28];
    const float* ylo  = (const float*)d_in[29];
    const float* yhi  = (const float*)d_in[30];

    cudaFuncSetAttribute(sim_kernel,
                         cudaFuncAttributeMaxDynamicSharedMemorySize,
                         (int)sizeof(SmemX));
    sim_kernel<<<B_ / BM, NT, sizeof(SmemX)>>>(
        xf0, xb0, uu, thf, thh,
        fW1, fb1, fbW1, fbb1, gbW1, gbb1, hW1, hb1, hbW1, hbb1,
        fW2, fb2, fbW2, fbb2, gbW2, gbb2, hW2, hb2, hbW2, hbb2,
        xlo, xhi, xblo, xbhi, ylo, yhi,
        (float*)d_out);
}

// round 12
// speedup vs baseline: 2.1456x; 1.2594x over previous
#include <cuda_runtime.h>

// ---------------------------------------------------------------------------
// RobustStateSpaceSimulatorAugmented: B=1024 rows, T=256 sequential steps.
// 128 CTAs x 512 threads, 8 rows per CTA, rows packed in pairs into f32x2.
//
// Numerics FROZEN: XLA EmitFastTanh, each dot = single ascending-k fp32x2 FMA
// chain, bias after dot, gate math op-for-op.
// R12: 3 phases/step (AD | B | C): D merged behind A (both depend only on
// prev C), E merged into C (owner-thread clip+store+scatter), unroll 4/8 for
// deeper LDG pipelining. Phase-B weight-shared dual chains kept from R11.
// ---------------------------------------------------------------------------

namespace {
constexpr int B_  = 1024;
constexpr int T_  = 256;
constexpr int NXF_ = 64;
constexpr int NXB_ = 32;
constexpr int NU_  = 16;
constexpr int NY_  = 16;
constexpr int NTH_ = 8;
constexpr int HID_ = 512;

constexpr int BM = 8;
constexpr int P  = BM / 2;
constexpr int NT = 512;

constexpr int DIN_F  = NXF_ + NU_  + NTH_;  // 88
constexpr int DIN_FB = NXF_ + NXB_ + NU_;   // 112
constexpr int DIN_H  = NXF_ + NTH_;         // 72
constexpr int DIN_HB = NXF_ + NXB_;         // 96

constexpr long OFF_XF = 0;
constexpr long OFF_XB = OFF_XF + (long)B_ * T_ * NXF_;
constexpr long OFF_Y  = OFF_XB + (long)B_ * T_ * NXB_;
constexpr long OFF_XP = OFF_Y  + (long)B_ * T_ * NY_;
} // namespace

typedef unsigned long long ull;

// ---------------------------------------------------------------------------
// f32x2 helpers
// ---------------------------------------------------------------------------
__device__ __forceinline__ ull pack2(float w) {
    ull r;
    asm("mov.b64 %0, {%1, %1};" : "=l"(r) : "f"(w));
    return r;
}

__device__ __forceinline__ float2 unpack2(ull v) {
    float2 r;
    asm("mov.b64 {%0, %1}, %2;" : "=f"(r.x), "=f"(r.y) : "l"(v));
    return r;
}

__device__ __forceinline__ void ffma2(ull& acc, ull a, ull b) {
    asm("fma.rn.f32x2 %0, %1, %2, %0;" : "+l"(acc) : "l"(a), "l"(b));
}

__device__ __forceinline__ float clipf(float v, float lo, float hi) {
    return fminf(fmaxf(v, lo), hi);
}

// XLA f32 tanh (EmitFastTanh / Eigen ptanh) — numerics frozen
__device__ __forceinline__ float xla_tanh(float x) {
    const float kMax = 7.90531110763549805f;
    float xc = fminf(fmaxf(x, -kMax), kMax);
    float x2 = xc * xc;
    float n = -2.76076847742355e-16f;
    n = fmaf(x2, n,  2.00018790482477e-13f);
    n = fmaf(x2, n, -8.60467152213735e-11f);
    n = fmaf(x2, n,  5.12229709037114e-08f);
    n = fmaf(x2, n,  1.48572235717979e-05f);
    n = fmaf(x2, n,  6.37261928875436e-04f);
    n = fmaf(x2, n,  4.89352455891786e-03f);
    n = xc * n;
    float d = 1.19825839466702e-06f;
    d = fmaf(x2, d, 1.18534705686654e-04f);
    d = fmaf(x2, d, 2.26843463243900e-03f);
    d = fmaf(x2, d, 4.89352518554385e-03f);
    float r = n / d;
    return fabsf(x) < 0.0004f ? x : r;
}

__device__ __forceinline__ float2 tanh2(ull acc, float bb) {
    float2 v = unpack2(acc);
    return make_float2(xla_tanh(v.x + bb), xla_tanh(v.y + bb));
}

// ---------------------------------------------------------------------------
// shared memory (~107 KB, 1 CTA/SM)
// ---------------------------------------------------------------------------
struct __align__(16) SmemX {
    float2 in_f [DIN_F  * P];  // [0,64) xp | [64,80) u | [80,88) thf
    float2 in_fb[DIN_FB * P];  // [0,64) xp | [64,96) xb | [96,112) u
    float2 in_h [DIN_H  * P];  // [0,64) xp | [64,72) thh
    float2 in_hb[DIN_HB * P];  // [0,64) xf | [64,96) xb   (PRE-clip)
    float2 hidf [P * HID_];
    float2 hidfb[P * HID_];
    float2 hidgb[P * HID_];
    float2 hidh [P * HID_];
    float2 hidhb[P * HID_];
    float2 xp[P * NXF_], xf[P * NXF_];
    float2 xb[P * NXB_], mu[P * NXB_], sig[P * NXB_];
    float2 fo[P * NXF_], fbo[P * NXF_], gbo[P * NXB_];
    float2 yoh[P * NY_], yohb[P * NY_];
};

// ---------------------------------------------------------------------------
// L2 dots, compact scalar weights. Each output chain is the exact ascending-k
// sequence  ffma2(acc, w[2k2], h.x); ffma2(acc, w[2k2+1], h.y)  — frozen.
// ---------------------------------------------------------------------------

// one weight stream feeding TWO independent chains (outputs (j,p0),(j,p1))
template <int DOUT>
__device__ __forceinline__ void dot512_2p(const float* __restrict__ W2,
                                          const float* __restrict__ b2, int j,
                                          const ulonglong2* __restrict__ hp0,
                                          const ulonglong2* __restrict__ hp1,
                                          float2& o0, float2& o1) {
    const float* w = W2 + j;
    ull a0 = 0ull, a1 = 0ull;
#pragma unroll 8
    for (int k2 = 0; k2 < HID_ / 2; k2++) {
        ull w0 = pack2(__ldg(w)); w += DOUT;
        ull w1 = pack2(__ldg(w)); w += DOUT;
        ulonglong2 h0 = hp0[k2], h1 = hp1[k2];
        ffma2(a0, w0, h0.x); ffma2(a0, w1, h0.y);
        ffma2(a1, w0, h1.x); ffma2(a1, w1, h1.y);
    }
    float bb = __ldg(b2 + j);
    o0 = unpack2(a0); o0.x += bb; o0.y += bb;
    o1 = unpack2(a1); o1.x += bb; o1.y += bb;
}

// single chain (epilogue only)
template <int DOUT>
__device__ __forceinline__ float2 dot512c(const float* __restrict__ W2,
                                          const float* __restrict__ b2, int j,
                                          const ulonglong2* __restrict__ hp2) {
    const float* w = W2 + j;
    ull acc = 0ull;
#pragma unroll 4
    for (int k2 = 0; k2 < HID_ / 2; k2++) {
        ull w0 = pack2(__ldg(w)); w += DOUT;
        ull w1 = pack2(__ldg(w)); w += DOUT;
        ulonglong2 h = hp2[k2];
        ffma2(acc, w0, h.x);
        ffma2(acc, w1, h.y);
    }
    float2 s = unpack2(acc);
    float bb = __ldg(b2 + j);
    s.x += bb; s.y += bb;
    return s;
}

// gating + mu/sigma (op-for-op vs reference; numerics frozen)
__device__ __forceinline__ void gate_update(float xb, float mu, float sig, float gbv,
                                            float t1, float t2, float xblo, float xbhi,
                                            float& xbn, float& mun, float& sgn) {
    float inv_gp  = 1.0f / sig;
    float inv_gp2 = 1.0f / (sig * sig);
    float xmmu = xb - mu;
    float delta1 = gbv * (xmmu + (gbv * 0.5f) * (1.0f + inv_gp));
    float delta2 = 1.0f - inv_gp;
    float delta = delta1 * delta2;
    float eps = t2 * (sig * sig - t2 / t1)
              + xmmu * (xmmu + gbv * (1.0f + inv_gp)
                        + (gbv * gbv * 0.5f) * (1.0f + inv_gp2));
    float d2e2 = delta * delta - eps * eps;
    bool c = ((eps >= delta) && (delta >= 0.0f))
          || ((eps <  delta) && (delta <  0.0f))
          || ((delta < eps)  && (eps  <  0.0f))
          || (((2.0f * t2 * t2 / t1) * eps >= d2e2) && (d2e2 > 0.0f));
    float gamma = c ? sig : 1.0f;
    float dxb = gbv / gamma;
    xbn = dxb;
    float xbc = fminf(fmaxf(dxb, xblo), xbhi);
    float c1 = t1 / t2;
    float c2 = 1.0f / t2;
    mun = c1 * mu + c2 * xbc;
    float dm = xbc - mun;
    sgn = sqrtf(c1 * (sig * sig) + c2 * (dm * dm));
}

// ---------------------------------------------------------------------------
// phase D part: fused h/hb L1, compact coalesced scalar weight loads
// ---------------------------------------------------------------------------
__device__ __forceinline__ void phaseD(SmemX& sm, int tid,
                                       const float* __restrict__ hW1,
                                       const float* __restrict__ hbW1,
                                       const float* __restrict__ hb1,
                                       const float* __restrict__ hbb1) {
    const int j = tid;
    const float* wh = hW1 + j;
    const float* wb = hbW1 + j;
    const ulonglong2* inh = reinterpret_cast<const ulonglong2*>(sm.in_h);
    const ulonglong2* inb = reinterpret_cast<const ulonglong2*>(sm.in_hb);
    ull ah0 = 0, ah1 = 0, ah2 = 0, ah3 = 0;
    ull ab0 = 0, ab1 = 0, ab2 = 0, ab3 = 0;
#pragma unroll 4
    for (int k = 0; k < DIN_H; k++) {
        ull wwh = pack2(__ldg(wh)); wh += HID_;
        ull wwb = pack2(__ldg(wb)); wb += HID_;
        ulonglong2 ha = inh[2 * k], hc = inh[2 * k + 1];
        ulonglong2 ba = inb[2 * k], bc = inb[2 * k + 1];
        ffma2(ah0, wwh, ha.x); ffma2(ah1, wwh, ha.y);
        ffma2(ah2, wwh, hc.x); ffma2(ah3, wwh, hc.y);
        ffma2(ab0, wwb, ba.x); ffma2(ab1, wwb, ba.y);
        ffma2(ab2, wwb, bc.x); ffma2(ab3, wwb, bc.y);
    }
#pragma unroll 4
    for (int k = DIN_H; k < DIN_HB; k++) {
        ull wwb = pack2(__ldg(wb)); wb += HID_;
        ulonglong2 ba = inb[2 * k], bc = inb[2 * k + 1];
        ffma2(ab0, wwb, ba.x); ffma2(ab1, wwb, ba.y);
        ffma2(ab2, wwb, bc.x); ffma2(ab3, wwb, bc.y);
    }
    float bh = __ldg(hb1 + j), bb = __ldg(hbb1 + j);
    sm.hidh [0 * HID_ + j] = tanh2(ah0, bh);
    sm.hidh [1 * HID_ + j] = tanh2(ah1, bh);
    sm.hidh [2 * HID_ + j] = tanh2(ah2, bh);
    sm.hidh [3 * HID_ + j] = tanh2(ah3, bh);
    sm.hidhb[0 * HID_ + j] = tanh2(ab0, bb);
    sm.hidhb[1 * HID_ + j] = tanh2(ab1, bb);
    sm.hidhb[2 * HID_ + j] = tanh2(ab2, bb);
    sm.hidhb[3 * HID_ + j] = tanh2(ab3, bb);
}

// ---------------------------------------------------------------------------
// prologue-only: raw x row 0 stores + u_0 scatter (doclip=false semantics)
// ---------------------------------------------------------------------------
__device__ __forceinline__ void prologue_store(SmemX& sm, float* __restrict__ out,
                                               const float* __restrict__ u,
                                               int b0, int tid) {
    if (tid < 256) {
#pragma unroll
        for (int r = 0; r < 2; r++) {
            int e = (tid << 1) | r;
            int bm = e >> 6, i = e & 63;
            int p = bm >> 1, lane = bm & 1;
            int si = ((p * NXF_ + i) << 1) | lane;
            float vf = reinterpret_cast<float*>(sm.xf)[si];
            float vp = reinterpret_cast<float*>(sm.xp)[si];
            size_t base = ((size_t)(b0 + bm) * T_ + 0);
            out[OFF_XF + base * NXF_ + i] = vf;
            out[OFF_XP + base * NXF_ + i] = vp;
        }
    } else if (tid < 384) {
#pragma unroll
        for (int r = 0; r < 2; r++) {
            int e = (((tid - 256) << 1) | r);
            int bm = e >> 5, i = e & 31;
            int p = bm >> 1, lane = bm & 1;
            int si = ((p * NXB_ + i) << 1) | lane;
            float v = reinterpret_cast<float*>(sm.xb)[si];
            out[OFF_XB + ((size_t)(b0 + bm) * T_ + 0) * NXB_ + i] = v;
        }
    } else {   // u[:, 0, :] into in_f [64,80) and in_fb [96,112)
        int e = tid - 384;
        int bm = e >> 4, i = e & 15;
        int p = bm >> 1, lane = bm & 1;
        float v = u[((size_t)(b0 + bm) * T_ + 0) * NU_ + i];
        reinterpret_cast<float*>(sm.in_f )[((((64 + i) << 2) | p) << 1) | lane] = v;
        reinterpret_cast<float*>(sm.in_fb)[((((96 + i) << 2) | p) << 1) | lane] = v;
    }
}

// ---------------------------------------------------------------------------
// main persistent kernel
// ---------------------------------------------------------------------------
__global__ void __launch_bounds__(NT, 1)
sim_kernel(const float* __restrict__ xf0, const float* __restrict__ xb0,
           const float* __restrict__ u,   const float* __restrict__ thfg,
           const float* __restrict__ thhg,
           const float* __restrict__ fW1,  const float* __restrict__ fb1,
           const float* __restrict__ fbW1, const float* __restrict__ fbb1,
           const float* __restrict__ gbW1, const float* __restrict__ gbb1,
           const float* __restrict__ hW1,  const float* __restrict__ hb1,
           const float* __restrict__ hbW1, const float* __restrict__ hbb1,
           const float* __restrict__ fW2,  const float* __restrict__ fb2_,
           const float* __restrict__ fbW2, const float* __restrict__ fbb2,
           const float* __restrict__ gbW2, const float* __restrict__ gbb2,
           const float* __restrict__ hW2,  const float* __restrict__ hb2_,
           const float* __restrict__ hbW2, const float* __restrict__ hbb2,
           const float* __restrict__ pxlo, const float* __restrict__ pxhi,
           const float* __restrict__ pxblo,const float* __restrict__ pxbhi,
           const float* __restrict__ pylo, const float* __restrict__ pyhi,
           float* __restrict__ out) {
    extern __shared__ __align__(16) char dynraw[];
    SmemX& sm = *reinterpret_cast<SmemX*>(dynraw);

    const int tid = threadIdx.x;
    const int b0  = blockIdx.x * BM;
    const float xlo = pxlo[0], xhi = pxhi[0];
    const float xblo = pxblo[0], xbhi = pxbhi[0];
    const float ylo = pylo[0], yhi = pyhi[0];

    // ---- prologue: initial state + static input segments ----
    {   // xf0 -> xp/xf state + scatter into all four input buffers
        int bm = tid >> 6, i = tid & 63;
        int p = bm >> 1, lane = bm & 1;
        float v = xf0[(b0 + bm) * NXF_ + i];
        int si = ((p * NXF_ + i) << 1) | lane;
        reinterpret_cast<float*>(sm.xf)[si] = v;
        reinterpret_cast<float*>(sm.xp)[si] = v;
        int ii = (((i << 2) | p) << 1) | lane;
        reinterpret_cast<float*>(sm.in_f )[ii] = v;
        reinterpret_cast<float*>(sm.in_fb)[ii] = v;
        reinterpret_cast<float*>(sm.in_h )[ii] = v;
        reinterpret_cast<float*>(sm.in_hb)[ii] = v;
    }
    if (tid < 256) {   // xb0 + mu/sig init + scatter
        int bm = tid >> 5, i = tid & 31;
        int p = bm >> 1, lane = bm & 1;
        float v = xb0[(b0 + bm) * NXB_ + i];
        int si = ((p * NXB_ + i) << 1) | lane;
        reinterpret_cast<float*>(sm.xb)[si]  = v;
        reinterpret_cast<float*>(sm.mu)[si]  = 0.0f;
        reinterpret_cast<float*>(sm.sig)[si] = 1.0f;
        int ii = ((((64 + i) << 2) | p) << 1) | lane;
        reinterpret_cast<float*>(sm.in_fb)[ii] = v;
        reinterpret_cast<float*>(sm.in_hb)[ii] = v;
    }
    if (tid < 64) {    // thetas
        int bm = tid >> 3, i = tid & 7;
        int p = bm >> 1, lane = bm & 1;
        reinterpret_cast<float*>(sm.in_f)[((((64 + NU_ + i) << 2) | p) << 1) | lane] =
            thfg[(b0 + bm) * NTH_ + i];
        reinterpret_cast<float*>(sm.in_h)[((((64 + i) << 2) | p) << 1) | lane] =
            thhg[(b0 + bm) * NTH_ + i];
    }
    __syncthreads();

    // store raw x row 0 + u_0 scatter
    prologue_store(sm, out, u, b0, tid);
    __syncthreads();

    // ---- main recurrence: iteration t computes state_{t+1}; stores y_t ----
    for (int t = 0; t < T_ - 1; t++) {
        const float tf = (float)t;

        // ===== phase AD: A-part (f/fb/gb L1) then D-part (h/hb L1) =====
        {
            const int j = tid;
            const float* wf = fW1 + j;
            const float* wb = fbW1 + j;
            const float* wg = gbW1 + j;
            const ulonglong2* inf = reinterpret_cast<const ulonglong2*>(sm.in_f);
            const ulonglong2* inb = reinterpret_cast<const ulonglong2*>(sm.in_fb);
            ull af0 = 0, af1 = 0, af2 = 0, af3 = 0;
            ull ab0 = 0, ab1 = 0, ab2 = 0, ab3 = 0;
            ull ag0 = 0, ag1 = 0, ag2 = 0, ag3 = 0;
#pragma unroll 4
            for (int k = 0; k < DIN_F; k++) {
                ull wwf = pack2(__ldg(wf)); wf += HID_;
                ull wwb = pack2(__ldg(wb)); wb += HID_;
                ull wwg = pack2(__ldg(wg)); wg += HID_;
                ulonglong2 fa = inf[2 * k], fc = inf[2 * k + 1];
                ulonglong2 ba = inb[2 * k], bc = inb[2 * k + 1];
                ffma2(af0, wwf, fa.x); ffma2(af1, wwf, fa.y);
                ffma2(af2, wwf, fc.x); ffma2(af3, wwf, fc.y);
                ffma2(ab0, wwb, ba.x); ffma2(ab1, wwb, ba.y);
                ffma2(ab2, wwb, bc.x); ffma2(ab3, wwb, bc.y);
                ffma2(ag0, wwg, ba.x); ffma2(ag1, wwg, ba.y);
                ffma2(ag2, wwg, bc.x); ffma2(ag3, wwg, bc.y);
            }
#pragma unroll 4
            for (int k = DIN_F; k < DIN_FB; k++) {
                ull wwb = pack2(__ldg(wb)); wb += HID_;
                ull wwg = pack2(__ldg(wg)); wg += HID_;
                ulonglong2 ba = inb[2 * k], bc = inb[2 * k + 1];
                ffma2(ab0, wwb, ba.x); ffma2(ab1, wwb, ba.y);
                ffma2(ab2, wwb, bc.x); ffma2(ab3, wwb, bc.y);
                ffma2(ag0, wwg, ba.x); ffma2(ag1, wwg, ba.y);
                ffma2(ag2, wwg, bc.x); ffma2(ag3, wwg, bc.y);
            }
            float bf = __ldg(fb1 + j), bb = __ldg(fbb1 + j), bg = __ldg(gbb1 + j);
            sm.hidf [0 * HID_ + j] = tanh2(af0, bf);
            sm.hidf [1 * HID_ + j] = tanh2(af1, bf);
            sm.hidf [2 * HID_ + j] = tanh2(af2, bf);
            sm.hidf [3 * HID_ + j] = tanh2(af3, bf);
            sm.hidfb[0 * HID_ + j] = tanh2(ab0, bb);
            sm.hidfb[1 * HID_ + j] = tanh2(ab1, bb);
            sm.hidfb[2 * HID_ + j] = tanh2(ab2, bb);
            sm.hidfb[3 * HID_ + j] = tanh2(ab3, bb);
            sm.hidgb[0 * HID_ + j] = tanh2(ag0, bg);
            sm.hidgb[1 * HID_ + j] = tanh2(ag1, bg);
            sm.hidgb[2 * HID_ + j] = tanh2(ag2, bg);
            sm.hidgb[3 * HID_ + j] = tanh2(ag3, bg);
        }
        // D-part: no barrier needed (also depends only on previous phase C)
        phaseD(sm, tid, hW1, hbW1, hb1, hbb1);
        __syncthreads();

        // ===== phase B: weight-shared dual-chain L2 dots (384 threads) =====
        //   f: 0-127 | fb: 128-255 | gb: 256-319 | h: 320-351 | hb: 352-383
        if (tid < 128) {
            const int j = tid & 63, pg = tid >> 6;
            const ulonglong2* hp0 = reinterpret_cast<const ulonglong2*>(
                sm.hidf + (2 * pg) * HID_);
            const ulonglong2* hp1 = reinterpret_cast<const ulonglong2*>(
                sm.hidf + (2 * pg + 1) * HID_);
            float2 o0, o1;
            dot512_2p<NXF_>(fW2, fb2_, j, hp0, hp1, o0, o1);
            sm.fo[(2 * pg) * NXF_ + j]     = o0;
            sm.fo[(2 * pg + 1) * NXF_ + j] = o1;
        } else if (tid < 256) {
            const int q = tid - 128, j = q & 63, pg = q >> 6;
            const ulonglong2* hp0 = reinterpret_cast<const ulonglong2*>(
                sm.hidfb + (2 * pg) * HID_);
            const ulonglong2* hp1 = reinterpret_cast<const ulonglong2*>(
                sm.hidfb + (2 * pg + 1) * HID_);
            float2 o0, o1;
            dot512_2p<NXF_>(fbW2, fbb2, j, hp0, hp1, o0, o1);
            sm.fbo[(2 * pg) * NXF_ + j]     = o0;
            sm.fbo[(2 * pg + 1) * NXF_ + j] = o1;
        } else if (tid < 320) {
            const int q = tid - 256, j = q & 31, pg = q >> 5;
            const ulonglong2* hp0 = reinterpret_cast<const ulonglong2*>(
                sm.hidgb + (2 * pg) * HID_);
            const ulonglong2* hp1 = reinterpret_cast<const ulonglong2*>(
                sm.hidgb + (2 * pg + 1) * HID_);
            float2 o0, o1;
            dot512_2p<NXB_>(gbW2, gbb2, j, hp0, hp1, o0, o1);
            sm.gbo[(2 * pg) * NXB_ + j]     = o0;
            sm.gbo[(2 * pg + 1) * NXB_ + j] = o1;
        } else if (tid < 352) {
            const int q = tid - 320, j = q & 15, pg = q >> 4;
            const ulonglong2* hp0 = reinterpret_cast<const ulonglong2*>(
                sm.hidh + (2 * pg) * HID_);
            const ulonglong2* hp1 = reinterpret_cast<const ulonglong2*>(
                sm.hidh + (2 * pg + 1) * HID_);
            float2 o0, o1;
            dot512_2p<NY_>(hW2, hb2_, j, hp0, hp1, o0, o1);
            sm.yoh[(2 * pg) * NY_ + j]     = o0;
            sm.yoh[(2 * pg + 1) * NY_ + j] = o1;
        } else if (tid < 384) {
            const int q = tid - 352, j = q & 15, pg = q >> 4;
            const ulonglong2* hp0 = reinterpret_cast<const ulonglong2*>(
                sm.hidhb + (2 * pg) * HID_);
            const ulonglong2* hp1 = reinterpret_cast<const ulonglong2*>(
                sm.hidhb + (2 * pg + 1) * HID_);
            float2 o0, o1;
            dot512_2p<NY_>(hbW2, hbb2, j, hp0, hp1, o0, o1);
            sm.yohb[(2 * pg) * NY_ + j]     = o0;
            sm.yohb[(2 * pg + 1) * NY_ + j] = o1;
        }
        __syncthreads();

        // ===== phase C (merged C+E): owner-thread update+clip+store+scatter
        if (tid < 128) {
            // xb gate: element (p,i) covers rows 2p (x) and 2p+1 (y)
            int q = tid, p = q >> 5, i = q & 31;
            float2 xb2 = sm.xb[q], mu2 = sm.mu[q], sg2 = sm.sig[q], gb2 = sm.gbo[q];
            float xbn, mun, sgn;
            gate_update(xb2.x, mu2.x, sg2.x, gb2.x, tf + 1.0f, tf + 2.0f,
                        xblo, xbhi, xbn, mun, sgn);
            xb2.x = xbn; mu2.x = mun; sg2.x = sgn;
            gate_update(xb2.y, mu2.y, sg2.y, gb2.y, tf + 1.0f, tf + 2.0f,
                        xblo, xbhi, xbn, mun, sgn);
            xb2.y = xbn; mu2.y = mun; sg2.y = sgn;
            sm.mu[q] = mu2; sm.sig[q] = sg2;
            sm.in_hb[((64 + i) << 2) | p] = xb2;        // pre-clip xb_{t+1}
            float2 xbc = make_float2(clipf(xb2.x, xblo, xbhi),
                                     clipf(xb2.y, xblo, xbhi));
            sm.xb[q] = xbc;                             // clipped carry
            sm.in_fb[((64 + i) << 2) | p] = xbc;        // next-step f_b/g_b input
            out[OFF_XB + ((size_t)(b0 + 2 * p)     * T_ + (t + 1)) * NXB_ + i] = xbc.x;
            out[OFF_XB + ((size_t)(b0 + 2 * p + 1) * T_ + (t + 1)) * NXB_ + i] = xbc.y;
        } else if (tid < 384) {
            // xp/xf update: element (p,i) covers rows 2p, 2p+1
            int q = tid - 128, p = q >> 6, i = q & 63;
            float2 xp2 = sm.xp[q], xf2 = sm.xf[q], f2 = sm.fo[q], fb2 = sm.fbo[q];
            float dfx = f2.x + fb2.x, dfy = f2.y + fb2.y;
            float2 xpn = make_float2(xp2.x + f2.x, xp2.y + f2.y);
            float2 xfn = make_float2(xf2.x + dfx, xf2.y + dfy);
            sm.in_h [(i << 2) | p] = xpn;               // pre-clip xp_{t+1}
            sm.in_hb[(i << 2) | p] = xfn;               // pre-clip xf_{t+1}
            float2 xpc = make_float2(clipf(xpn.x, xlo, xhi), clipf(xpn.y, xlo, xhi));
            float2 xfc = make_float2(clipf(xfn.x, xlo, xhi), clipf(xfn.y, xlo, xhi));
            sm.xp[q] = xpc; sm.xf[q] = xfc;             // clipped carry
            sm.in_f [(i << 2) | p] = xpc;               // next-step f input
            sm.in_fb[(i << 2) | p] = xpc;               // next-step fb/gb input
            size_t b0a = ((size_t)(b0 + 2 * p)     * T_ + (t + 1));
            size_t b0b = ((size_t)(b0 + 2 * p + 1) * T_ + (t + 1));
            out[OFF_XF + b0a * NXF_ + i] = xfc.x;
            out[OFF_XF + b0b * NXF_ + i] = xfc.y;
            out[OFF_XP + b0a * NXF_ + i] = xpc.x;
            out[OFF_XP + b0b * NXF_ + i] = xpc.y;
        } else {
            // y_t store (raw at t=0, clipped after) + u_{t+1} prefetch
            int e = tid - 384;
            int bm = e >> 4, i = e & 15;
            int p = bm >> 1, lane = bm & 1;
            int si = ((p * NY_ + i) << 1) | lane;
            float v = reinterpret_cast<float*>(sm.yoh)[si]
                    + reinterpret_cast<float*>(sm.yohb)[si];
            if (t > 0) v = clipf(v, ylo, yhi);
            out[OFF_Y + ((size_t)(b0 + bm) * T_ + t) * NY_ + i] = v;
            float uv = u[((size_t)(b0 + bm) * T_ + (t + 1)) * NU_ + i];
            reinterpret_cast<float*>(sm.in_f )[((((64 + i) << 2) | p) << 1) | lane] = uv;
            reinterpret_cast<float*>(sm.in_fb)[((((96 + i) << 2) | p) << 1) | lane] = uv;
        }
        __syncthreads();
    }

    // ---- epilogue: D for state_255, then y_255 dots + clipped store ----
    phaseD(sm, tid, hW1, hbW1, hb1, hbb1);
    __syncthreads();
    if (tid < 128) {
        const bool isH = tid < 64;
        const int q = isH ? tid : tid - 64;
        const int j = q & 15, p = q >> 4;
        const ulonglong2* hp = reinterpret_cast<const ulonglong2*>(
            (isH ? sm.hidh : sm.hidhb) + p * HID_);
        float2 r = dot512c<NY_>(isH ? hW2 : hbW2, isH ? hb2_ : hbb2, j, hp);
        (isH ? sm.yoh : sm.yohb)[p * NY_ + j] = r;
    }
    __syncthreads();
    if (tid < 128) {
        int bm = tid >> 4, i = tid & 15;
        int si = (((bm >> 1) * NY_ + i) << 1) | (bm & 1);
        float v = reinterpret_cast<float*>(sm.yoh)[si]
                + reinterpret_cast<float*>(sm.yohb)[si];
        v = clipf(v, ylo, yhi);
        out[OFF_Y + ((size_t)(b0 + bm) * T_ + (T_ - 1)) * NY_ + i] = v;
    }
}

// ---------------------------------------------------------------------------
extern "C" void kernel_launch(void* const* d_in, const int* in_sizes, int n_in,
                              void* d_out, int out_size) {
    (void)in_sizes; (void)n_in; (void)out_size;
    const float* xf0  = (const float*)d_in[0];
    const float* xb0  = (const float*)d_in[1];
    const float* uu   = (const float*)d_in[2];
    const float* thf  = (const float*)d_in[3];
    const float* thh  = (const float*)d_in[4];
    const float* fW1  = (const float*)d_in[5];
    const float* fb1  = (const float*)d_in[6];
    const float* fW2  = (const float*)d_in[7];
    const float* fb2  = (const float*)d_in[8];
    const float* fbW1 = (const float*)d_in[9];
    const float* fbb1 = (const float*)d_in[10];
    const float* fbW2 = (const float*)d_in[11];
    const float* fbb2 = (const float*)d_in[12];
    const float* gbW1 = (const float*)d_in[13];
    const float* gbb1 = (const float*)d_in[14];
    const float* gbW2 = (const float*)d_in[15];
    const float* gbb2 = (const float*)d_in[16];
    const float* hW1  = (const float*)d_in[17];
    const float* hb1  = (const float*)d_in[18];
    const float* hW2  = (const float*)d_in[19];
    const float* hb2  = (const float*)d_in[20];
    const float* hbW1 = (const float*)d_in[21];
    const float* hbb1 = (const float*)d_in[22];
    const float* hbW2 = (const float*)d_in[23];
    const float* hbb2 = (const float*)d_in[24];
    const float* xlo  = (const float*)d_in[25];
    const float* xhi  = (const float*)d_in[26];
    const float* xblo = (const float*)d_in[27];
    const float* xbhi = (const float*)d_in[28];
    const float* ylo  = (const float*)d_in[29];
    const float* yhi  = (const float*)d_in[30];

    cudaFuncSetAttribute(sim_kernel,
                         cudaFuncAttributeMaxDynamicSharedMemorySize,
                         (int)sizeof(SmemX));
    sim_kernel<<<B_ / BM, NT, sizeof(SmemX)>>>(
        xf0, xb0, uu, thf, thh,
        fW1, fb1, fbW1, fbb1, gbW1, gbb1, hW1, hb1, hbW1, hbb1,
        fW2, fb2, fbW2, fbb2, gbW2, gbb2, hW2, hb2, hbW2, hbb2,
        xlo, xhi, xblo, xbhi, ylo, yhi,
        (float*)d_out);
}